// round 6
// baseline (speedup 1.0000x reference)
#include <cuda_runtime.h>
#include <cuda_fp16.h>
#include <cstdint>

#define SEQ 1024
#define DIMC 1024
#define NHEADS 16
#define HDIM 64
#define NBATCH 2
#define NBH (NBATCH*NHEADS)   // 32

typedef unsigned long long ull;

// ---------------- scratch (device globals; no runtime allocation) -------------
__device__ float  g_qkv[3][NBH][SEQ][HDIM];    // 24 MB  q/k/v [bh][s][d]
__device__ __half g_kern_h[NBH][SEQ][SEQ];     // 67 MB  fp16 kernel matrix
__device__ float  g_rowsum[NBH][SEQ];          // row sums (fp32)
// fp16 hi/lo split operands for the tensor-core GEMMs
__device__ __half g_xh[2048*1024],  g_xl[2048*1024];     // x
__device__ __half g_wqh[3072*1024], g_wql[3072*1024];    // qkv_w
__device__ __half g_wph[1024*1024], g_wpl[1024*1024];    // proj_w
__device__ __half g_yh[2048*1024],  g_yl[2048*1024];     // pre-projection act.

// ---------------- helpers ------------------------------------------------------
__device__ __forceinline__ ull f2add(ull a, ull b) {
    ull d; asm("add.rn.f32x2 %0, %1, %2;" : "=l"(d) : "l"(a), "l"(b)); return d;
}
__device__ __forceinline__ ull pk2(float x, float y) {
    return (ull)__float_as_uint(x) | ((ull)__float_as_uint(y) << 32);
}
__device__ __forceinline__ uint32_t smem_u32(const void* p) {
    return (uint32_t)__cvta_generic_to_shared(p);
}
__device__ __forceinline__ void cp16(uint32_t s, const void* g) {
    asm volatile("cp.async.cg.shared.global [%0], [%1], 16;\n" :: "r"(s), "l"(g));
}
__device__ __forceinline__ void mma_f16(float c[4],
        uint32_t a0, uint32_t a1, uint32_t a2, uint32_t a3,
        uint32_t b0, uint32_t b1) {
    asm volatile(
        "mma.sync.aligned.m16n8k16.row.col.f32.f16.f16.f32 "
        "{%0,%1,%2,%3}, {%4,%5,%6,%7}, {%8,%9}, {%0,%1,%2,%3};"
        : "+f"(c[0]), "+f"(c[1]), "+f"(c[2]), "+f"(c[3])
        : "r"(a0), "r"(a1), "r"(a2), "r"(a3), "r"(b0), "r"(b1));
}
__device__ __forceinline__ void ldsm4(uint32_t& r0, uint32_t& r1,
                                      uint32_t& r2, uint32_t& r3, uint32_t a) {
    asm volatile("ldmatrix.sync.aligned.m8n8.x4.shared.b16 {%0,%1,%2,%3}, [%4];"
                 : "=r"(r0), "=r"(r1), "=r"(r2), "=r"(r3) : "r"(a));
}
__device__ __forceinline__ void ldsm2t(uint32_t& r0, uint32_t& r1, uint32_t a) {
    asm volatile("ldmatrix.sync.aligned.m8n8.x2.trans.shared.b16 {%0,%1}, [%2];"
                 : "=r"(r0), "=r"(r1) : "r"(a));
}
__device__ __forceinline__ uint32_t h2u(__half2 h) { return *(uint32_t*)&h; }

// ==============================================================================
// Prepass: split x / qkv_w / proj_w into fp16 hi/lo scratch pairs.
// ==============================================================================
__global__ __launch_bounds__(256) void prep_f16(const float* __restrict__ x,
                                                const float* __restrict__ wq,
                                                const float* __restrict__ wp)
{
    const float4* src; __half* dh; __half* dl; int n4;
    if (blockIdx.y == 0)      { src = (const float4*)x;  dh = g_xh;  dl = g_xl;  n4 = 524288; }
    else if (blockIdx.y == 1) { src = (const float4*)wq; dh = g_wqh; dl = g_wql; n4 = 786432; }
    else                      { src = (const float4*)wp; dh = g_wph; dl = g_wpl; n4 = 262144; }
    int i = blockIdx.x * 256 + threadIdx.x;
    if (i < n4) {
        float4 v = src[i];
        __half hx = __float2half_rn(v.x), hy = __float2half_rn(v.y);
        __half hz = __float2half_rn(v.z), hw = __float2half_rn(v.w);
        __half lx = __float2half_rn(v.x - __half2float(hx));
        __half ly = __float2half_rn(v.y - __half2float(hy));
        __half lz = __float2half_rn(v.z - __half2float(hz));
        __half lw = __float2half_rn(v.w - __half2float(hw));
        ((uint2*)dh)[i] = make_uint2(h2u(__halves2half2(hx, hy)),
                                     h2u(__halves2half2(hz, hw)));
        ((uint2*)dl)[i] = make_uint2(h2u(__halves2half2(lx, ly)),
                                     h2u(__halves2half2(lz, lw)));
    }
}

// ==============================================================================
// fp16 split-precision tensor-core GEMM (NT): C = A @ B^T + bias
// A,B given as fp16 (hi,lo) pairs; acc += Ah*Bh + Ah*Bl + Al*Bh  (fp32 acc).
// BM=BN=128, BK=32, 256 thr / 8 warps (4Mx2N), warptile 32x64, 2-stage cp.async.
// MODE 1: A=x, B=qkv_w, scatter to g_qkv.  MODE 0: A=y, B=proj_w, row-major C.
// smem stage: Ah | Al | Bh | Bl, each 128 rows x 40 halves (80 B stride).
// ==============================================================================
#define HG_STAGE 40960
#define HG_SMEM  (2*HG_STAGE)

template<int MODE>
__global__ __launch_bounds__(256, 2) void hgemm_nt(
    const float* __restrict__ bias, float* __restrict__ C, int N, int K)
{
    extern __shared__ char smh[];
    const uint32_t smB = smem_u32(smh);

    const int tid  = threadIdx.x;
    const int warp = tid >> 5;
    const int lane = tid & 31;
    const int gr   = lane >> 2;
    const int tg   = lane & 3;
    const int wm   = (warp & 3) * 32;
    const int wn   = (warp >> 2) * 64;
    const int mb   = blockIdx.y * 128;
    const int nb   = blockIdx.x * 128;

    const __half* AH = (MODE == 1) ? g_xh  : g_yh;
    const __half* AL = (MODE == 1) ? g_xl  : g_yl;
    const __half* BH = (MODE == 1) ? g_wqh : g_wph;
    const __half* BL = (MODE == 1) ? g_wql : g_wpl;

    // staging: 256 threads, each 2 chunks of 16B per operand array
    const int row = tid >> 1;
    const int cp  = (tid & 1) * 2;
    const __half* aHg = AH + (size_t)(mb + row) * K + cp * 8;
    const __half* aLg = AL + (size_t)(mb + row) * K + cp * 8;
    const __half* bHg = BH + (size_t)(nb + row) * K + cp * 8;
    const __half* bLg = BL + (size_t)(nb + row) * K + cp * 8;
    const uint32_t stDst = row * 80 + cp * 16;

    auto load_st = [&](int st, int k0) {
        const uint32_t d = smB + st * HG_STAGE + stDst;
        cp16(d,              aHg + k0); cp16(d + 16,         aHg + k0 + 8);
        cp16(d + 10240,      aLg + k0); cp16(d + 10240 + 16, aLg + k0 + 8);
        cp16(d + 20480,      bHg + k0); cp16(d + 20480 + 16, bHg + k0 + 8);
        cp16(d + 30720,      bLg + k0); cp16(d + 30720 + 16, bLg + k0 + 8);
        asm volatile("cp.async.commit_group;\n");
    };

    float acc[2][8][4];
#pragma unroll
    for (int i = 0; i < 2; i++)
#pragma unroll
        for (int j = 0; j < 8; j++)
#pragma unroll
            for (int r = 0; r < 4; r++) acc[i][j][r] = 0.f;

    const uint32_t aOff = (wm + (lane & 15)) * 80 + (lane >> 4) * 16;
    const uint32_t bOff = (wn + (lane & 15)) * 80 + (lane >> 4) * 16 + 20480;

    const int nK = K / 32;
    load_st(0, 0);

    for (int kt = 0; kt < nK; kt++) {
        asm volatile("cp.async.wait_group 0;\n");
        __syncthreads();
        if (kt + 1 < nK) load_st((kt + 1) & 1, (kt + 1) * 32);
        const uint32_t sb = smB + (kt & 1) * HG_STAGE;

#pragma unroll
        for (int s = 0; s < 2; s++) {
            uint32_t ah[2][4], al_[2][4];
#pragma unroll
            for (int i = 0; i < 2; i++) {
                ldsm4(ah[i][0], ah[i][1], ah[i][2], ah[i][3],
                      sb + aOff + i * 1280 + s * 32);
                ldsm4(al_[i][0], al_[i][1], al_[i][2], al_[i][3],
                      sb + aOff + i * 1280 + s * 32 + 10240);
            }
#pragma unroll
            for (int j = 0; j < 4; j++) {
                uint32_t bh_[4], bl_[4];
                ldsm4(bh_[0], bh_[1], bh_[2], bh_[3],
                      sb + bOff + j * 1280 + s * 32);
                ldsm4(bl_[0], bl_[1], bl_[2], bl_[3],
                      sb + bOff + j * 1280 + s * 32 + 10240);
#pragma unroll
                for (int i = 0; i < 2; i++) {
                    mma_f16(acc[i][2*j  ], ah[i][0], ah[i][1], ah[i][2], ah[i][3], bh_[0], bh_[2]);
                    mma_f16(acc[i][2*j+1], ah[i][0], ah[i][1], ah[i][2], ah[i][3], bh_[1], bh_[3]);
                    mma_f16(acc[i][2*j  ], ah[i][0], ah[i][1], ah[i][2], ah[i][3], bl_[0], bl_[2]);
                    mma_f16(acc[i][2*j+1], ah[i][0], ah[i][1], ah[i][2], ah[i][3], bl_[1], bl_[3]);
                    mma_f16(acc[i][2*j  ], al_[i][0], al_[i][1], al_[i][2], al_[i][3], bh_[0], bh_[2]);
                    mma_f16(acc[i][2*j+1], al_[i][0], al_[i][1], al_[i][2], al_[i][3], bh_[1], bh_[3]);
                }
            }
        }
    }

    // epilogue (m16n8 fragment layout)
#pragma unroll
    for (int i = 0; i < 2; i++) {
#pragma unroll
        for (int j = 0; j < 8; j++) {
            const int r0 = mb + wm + i * 16 + gr;
            const int c0 = nb + wn + j * 8 + 2 * tg;
            const float bia0 = bias[c0], bia1 = bias[c0 + 1];
            if (MODE == 1) {
#pragma unroll
                for (int e = 0; e < 4; e++) {
                    const int m = r0 + (e >> 1) * 8;
                    const int n = c0 + (e & 1);
                    const float v = acc[i][j][e] + ((e & 1) ? bia1 : bia0);
                    const int tsel = n >> 10, rem = n & 1023;
                    const int h = rem >> 6, d = rem & 63;
                    const int bb = m >> 10, s = m & 1023;
                    g_qkv[tsel][bb * NHEADS + h][s][d] = v;
                }
            } else {
                float2 lo = make_float2(acc[i][j][0] + bia0, acc[i][j][1] + bia1);
                float2 hi = make_float2(acc[i][j][2] + bia0, acc[i][j][3] + bia1);
                *(float2*)&C[(size_t)r0 * N + c0]       = lo;
                *(float2*)&C[(size_t)(r0 + 8) * N + c0] = hi;
            }
        }
    }
}

// ==============================================================================
// Laplacian kernel (standalone): kern fp16 + fp32 rowsum.
// Grid (16 i-tiles, 32 bh), 256 threads, 4x4 microtile, packed f32x2 L1 distance.
// ==============================================================================
__global__ __launch_bounds__(256) void laplace_kern()
{
    __shared__ ull qs[32][64];   // [d/2][i]
    __shared__ ull ks[32][64];   // [d/2][j]  (stores -k)

    const int tid = threadIdx.x;
    const int tx  = tid & 15;
    const int ty  = tid >> 4;
    const int it  = blockIdx.x;
    const int bh  = blockIdx.y;

    const float* Q  = &g_qkv[0][bh][it*64][0];
    const float* Kp = &g_qkv[1][bh][0][0];

#pragma unroll
    for (int r = 0; r < 4; r++) {
        int idx = r*1024 + tid*4;
        int i = idx >> 6, d = idx & 63;
        float4 v = *(const float4*)(Q + i*64 + d);
        qs[(d>>1)    ][i] = pk2(v.x, v.y);
        qs[(d>>1) + 1][i] = pk2(v.z, v.w);
    }

    float rs[4] = {0.f, 0.f, 0.f, 0.f};
    char* kout = (char*)&g_kern_h[bh][it*64][0];

    for (int jt = 0; jt < 16; jt++) {
#pragma unroll
        for (int r = 0; r < 4; r++) {
            int idx = r*1024 + tid*4;
            int j = idx >> 6, d = idx & 63;
            float4 v = *(const float4*)(Kp + (jt*64 + j)*64 + d);
            ks[(d>>1)    ][j] = pk2(-v.x, -v.y);
            ks[(d>>1) + 1][j] = pk2(-v.z, -v.w);
        }
        __syncthreads();

        ull a2[4][4];
#pragma unroll
        for (int ii = 0; ii < 4; ii++)
#pragma unroll
            for (int jj = 0; jj < 4; jj++) a2[ii][jj] = 0ull;

#pragma unroll
        for (int d2 = 0; d2 < 32; d2++) {
            ulonglong2 qa = *(const ulonglong2*)&qs[d2][ty*4];
            ulonglong2 qb = *(const ulonglong2*)&qs[d2][ty*4 + 2];
            ulonglong2 ka = *(const ulonglong2*)&ks[d2][tx*4];
            ulonglong2 kb = *(const ulonglong2*)&ks[d2][tx*4 + 2];
            ull q2[4] = {qa.x, qa.y, qb.x, qb.y};
            ull k2[4] = {ka.x, ka.y, kb.x, kb.y};
#pragma unroll
            for (int ii = 0; ii < 4; ii++)
#pragma unroll
                for (int jj = 0; jj < 4; jj++) {
                    ull t = f2add(q2[ii], k2[jj]) & 0x7FFFFFFF7FFFFFFFull;
                    a2[ii][jj] = f2add(a2[ii][jj], t);
                }
        }

#pragma unroll
        for (int ii = 0; ii < 4; ii++) {
            float op[4];
#pragma unroll
            for (int jj = 0; jj < 4; jj++) {
                ull v = a2[ii][jj];
                float dist = __uint_as_float((unsigned)v)
                           + __uint_as_float((unsigned)(v >> 32));
                float kv = __expf(-0.0625f * dist);
                op[jj] = kv;
                rs[ii] += kv;
            }
            __half2 p01 = __floats2half2_rn(op[0], op[1]);
            __half2 p23 = __floats2half2_rn(op[2], op[3]);
            *(uint2*)(kout + ((size_t)(ty*4 + ii)*1024 + jt*64 + tx*4)*2)
                = make_uint2(h2u(p01), h2u(p23));
        }
        __syncthreads();
    }

#pragma unroll
    for (int ii = 0; ii < 4; ii++) {
        float v = rs[ii];
        v += __shfl_xor_sync(0xffffffffu, v, 1);
        v += __shfl_xor_sync(0xffffffffu, v, 2);
        v += __shfl_xor_sync(0xffffffffu, v, 4);
        v += __shfl_xor_sync(0xffffffffu, v, 8);
        if (tx == 0) g_rowsum[bh][it*64 + ty*4 + ii] = v;
    }
}

// ==============================================================================
// attnv_tc: global = (kern_fp16 @ v) via m16n8k16 HMMA; v in fp16 hi/lo (2 mmas).
// + row normalize + depthwise conv; outputs y as fp16 hi/lo (g_yh/g_yl).
// ==============================================================================
#define AV_STAGE 36864
#define AV_SMEM  (2*AV_STAGE)

__global__ __launch_bounds__(256, 2) void attnv_tc(const float* __restrict__ dwc_w,
                                                   const float* __restrict__ dwc_b)
{
    extern __shared__ char sm[];
    const int tid  = threadIdx.x;
    const int warp = tid >> 5;
    const int lane = tid & 31;
    const int gr   = lane >> 2;
    const int tg   = lane & 3;
    const int it   = blockIdx.x;
    const int bh   = blockIdx.y;
    const int bb   = bh >> 4;
    const int h    = bh & 15;

    const __half* Kh = &g_kern_h[bh][0][0];
    const float*  V  = &g_qkv[2][bh][0][0];
    const uint32_t smBase = smem_u32(sm);

    float acc[8][4];
#pragma unroll
    for (int n = 0; n < 8; n++)
#pragma unroll
        for (int e = 0; e < 4; e++) acc[n][e] = 0.f;

    const int arow = tid >> 3, achk = tid & 7;
    const int vrow = tid >> 4, vd = (tid & 15) * 4;

    auto issue_kern = [&](int st, int k0) {
        const uint32_t dst = smBase + st * AV_STAGE;
#pragma unroll
        for (int q = 0; q < 4; q++) {
            int r = arow + 32 * q;
            cp16(dst + r * 144 + achk * 16,
                 Kh + (size_t)(it * 128 + r) * 1024 + k0 + achk * 8);
        }
        asm volatile("cp.async.commit_group;\n");
    };
    auto ldg_v = [&](int k0, float4* vr) {
#pragma unroll
        for (int q = 0; q < 4; q++)
            vr[q] = *(const float4*)(V + (size_t)(k0 + vrow + 16 * q) * 64 + vd);
    };
    auto sts_v = [&](int st, const float4* vr) {
        char* vhB = sm + st * AV_STAGE + 18432;
        char* vlB = sm + st * AV_STAGE + 27648;
#pragma unroll
        for (int q = 0; q < 4; q++) {
            int r = vrow + 16 * q;
            float4 vv = vr[q];
            __half hx = __float2half_rn(vv.x), hy = __float2half_rn(vv.y);
            __half hz = __float2half_rn(vv.z), hw = __float2half_rn(vv.w);
            __half2 hi0 = __halves2half2(hx, hy), hi1 = __halves2half2(hz, hw);
            __half2 lo0 = __floats2half2_rn(vv.x - __half2float(hx),
                                            vv.y - __half2float(hy));
            __half2 lo1 = __floats2half2_rn(vv.z - __half2float(hz),
                                            vv.w - __half2float(hw));
            *(uint2*)(vhB + r * 144 + vd * 2) = make_uint2(h2u(hi0), h2u(hi1));
            *(uint2*)(vlB + r * 144 + vd * 2) = make_uint2(h2u(lo0), h2u(lo1));
        }
    };

    const uint32_t aOff = (uint32_t)((warp * 16 + (lane & 7) + ((lane >> 3) & 1) * 8) * 144
                                     + (lane >> 4) * 16);
    const uint32_t bRow = (uint32_t)((lane & 15) * 144);

    issue_kern(0, 0);
    {
        float4 vr[4];
        ldg_v(0, vr);
        sts_v(0, vr);
    }

    for (int kt = 0; kt < 16; kt++) {
        const int cur = kt & 1;
        asm volatile("cp.async.wait_group 0;\n");
        __syncthreads();

        float4 vr[4];
        if (kt < 15) {
            issue_kern(cur ^ 1, (kt + 1) * 64);
            ldg_v((kt + 1) * 64, vr);
        }

        const uint32_t aB  = smBase + cur * AV_STAGE + aOff;
        const uint32_t vhB = smBase + cur * AV_STAGE + 18432 + bRow;
        const uint32_t vlB = smBase + cur * AV_STAGE + 27648 + bRow;
#pragma unroll
        for (int k16 = 0; k16 < 4; k16++) {
            uint32_t a0, a1, a2, a3;
            ldsm4(a0, a1, a2, a3, aB + k16 * 32);
#pragma unroll
            for (int nf = 0; nf < 8; nf++) {
                uint32_t bh0, bh1, bl0, bl1;
                ldsm2t(bh0, bh1, vhB + k16 * 2304 + nf * 16);
                ldsm2t(bl0, bl1, vlB + k16 * 2304 + nf * 16);
                mma_f16(acc[nf], a0, a1, a2, a3, bh0, bh1);
                mma_f16(acc[nf], a0, a1, a2, a3, bl0, bl1);
            }
        }

        if (kt < 15) sts_v(cur ^ 1, vr);
    }

    // ---- epilogue: normalize + depthwise conv; emit y as fp16 hi/lo ----
    const int m0 = it * 128 + warp * 16 + gr;
#pragma unroll
    for (int nf = 0; nf < 8; nf++) {
        const int dl = nf * 8 + tg * 2;
        const int c  = h * 64 + dl;
        const float w0a = dwc_w[c*3+0], w1a = dwc_w[c*3+1], w2a = dwc_w[c*3+2];
        const float b0a = dwc_b[c];
        const float w0b = dwc_w[c*3+3], w1b = dwc_w[c*3+4], w2b = dwc_w[c*3+5];
        const float b1b = dwc_b[c+1];
#pragma unroll
        for (int half = 0; half < 2; half++) {
            const int s = m0 + half * 8;
            const float sc = 1.0f / (g_rowsum[bh][s] + 1e-6f);
            float o0 = acc[nf][half*2 + 0] * sc;
            float o1 = acc[nf][half*2 + 1] * sc;
            float2 v0 = *(const float2*)&V[(size_t)s*64 + dl];
            float2 vm = (s > 0)       ? *(const float2*)&V[(size_t)(s-1)*64 + dl]
                                      : make_float2(0.f, 0.f);
            float2 vp = (s < SEQ - 1) ? *(const float2*)&V[(size_t)(s+1)*64 + dl]
                                      : make_float2(0.f, 0.f);
            o0 += w0a*vm.x + w1a*v0.x + w2a*vp.x + b0a;
            o1 += w0b*vm.y + w1b*v0.y + w2b*vp.y + b1b;
            __half h0 = __float2half_rn(o0);
            __half h1 = __float2half_rn(o1);
            __half l0 = __float2half_rn(o0 - __half2float(h0));
            __half l1 = __float2half_rn(o1 - __half2float(h1));
            const size_t oidx = (size_t)(bb*SEQ + s) * 1024 + c;
            *(uint32_t*)&g_yh[oidx] = h2u(__halves2half2(h0, h1));
            *(uint32_t*)&g_yl[oidx] = h2u(__halves2half2(l0, l1));
        }
    }
}

// ==============================================================================
extern "C" void kernel_launch(void* const* d_in, const int* in_sizes, int n_in,
                              void* d_out, int out_size)
{
    const float* x      = (const float*)d_in[0];
    const float* qkv_w  = (const float*)d_in[1];
    const float* qkv_b  = (const float*)d_in[2];
    const float* proj_w = (const float*)d_in[3];
    const float* proj_b = (const float*)d_in[4];
    const float* dwc_w  = (const float*)d_in[5];
    const float* dwc_b  = (const float*)d_in[6];
    float* out = (float*)d_out;

    cudaFuncSetAttribute(hgemm_nt<1>, cudaFuncAttributeMaxDynamicSharedMemorySize, HG_SMEM);
    cudaFuncSetAttribute(hgemm_nt<0>, cudaFuncAttributeMaxDynamicSharedMemorySize, HG_SMEM);
    cudaFuncSetAttribute(attnv_tc,    cudaFuncAttributeMaxDynamicSharedMemorySize, AV_SMEM);

    // 0) split x / weights into fp16 hi/lo scratch
    prep_f16<<<dim3(3072, 3), 256>>>(x, qkv_w, proj_w);
    // 1) qkv projection (fp16 split HMMA + ldmatrix), scatter to q/k/v (fp32)
    hgemm_nt<1><<<dim3(24, 16), 256, HG_SMEM>>>(qkv_b, nullptr, 3072, 1024);
    // 2) Laplacian L1 kernel matrix (fp16) + fp32 row sums
    laplace_kern<<<dim3(16, 32), 256>>>();
    // 3) kern_fp16 @ v (fp16 HMMA, v hi/lo) + normalize + dwc -> y (fp16 hi/lo)
    attnv_tc<<<dim3(8, 32), 256, AV_SMEM>>>(dwc_w, dwc_b);
    // 4) output projection (fp16 split HMMA) -> d_out
    hgemm_nt<0><<<dim3(8, 16), 256, HG_SMEM>>>(proj_b, out, 1024, 1024);
}

// round 7
// speedup vs baseline: 1.4002x; 1.4002x over previous
#include <cuda_runtime.h>
#include <cuda_fp16.h>
#include <cstdint>

#define SEQ 1024
#define DIMC 1024
#define NHEADS 16
#define HDIM 64
#define NBATCH 2
#define NBH (NBATCH*NHEADS)   // 32

typedef unsigned long long ull;

// ---------------- scratch (device globals; no runtime allocation) -------------
__device__ float  g_qkv[3][NBH][SEQ][HDIM];    // 24 MB  q/k/v [bh][s][d]
__device__ __half g_kern_h[NBH][SEQ][SEQ];     // 67 MB  fp16 kernel matrix
__device__ float  g_rowsum[NBH][SEQ];          // row sums (fp32)
__device__ float  g_y[NBATCH*SEQ][DIMC];       // 8 MB   pre-projection (tf32-rounded)
__device__ float  g_xr[2048*1024];             // tf32-rounded x
__device__ float  g_wqr[3072*1024];            // tf32-rounded qkv_w
__device__ float  g_wpr[1024*1024];            // tf32-rounded proj_w

// ---------------- helpers ------------------------------------------------------
__device__ __forceinline__ uint32_t smem_u32(const void* p) {
    return (uint32_t)__cvta_generic_to_shared(p);
}
__device__ __forceinline__ void cp16(uint32_t s, const void* g) {
    asm volatile("cp.async.cg.shared.global [%0], [%1], 16;\n" :: "r"(s), "l"(g));
}
__device__ __forceinline__ uint32_t f2tf32(float f) {
    uint32_t r; asm("cvt.rna.tf32.f32 %0, %1;" : "=r"(r) : "f"(f)); return r;
}
__device__ __forceinline__ void mma_tf32(float c[4],
        uint32_t a0, uint32_t a1, uint32_t a2, uint32_t a3,
        uint32_t b0, uint32_t b1) {
    asm volatile(
        "mma.sync.aligned.m16n8k8.row.col.f32.tf32.tf32.f32 "
        "{%0,%1,%2,%3}, {%4,%5,%6,%7}, {%8,%9}, {%0,%1,%2,%3};"
        : "+f"(c[0]), "+f"(c[1]), "+f"(c[2]), "+f"(c[3])
        : "r"(a0), "r"(a1), "r"(a2), "r"(a3), "r"(b0), "r"(b1));
}
__device__ __forceinline__ void mma_f16(float c[4],
        uint32_t a0, uint32_t a1, uint32_t a2, uint32_t a3,
        uint32_t b0, uint32_t b1) {
    asm volatile(
        "mma.sync.aligned.m16n8k16.row.col.f32.f16.f16.f32 "
        "{%0,%1,%2,%3}, {%4,%5,%6,%7}, {%8,%9}, {%0,%1,%2,%3};"
        : "+f"(c[0]), "+f"(c[1]), "+f"(c[2]), "+f"(c[3])
        : "r"(a0), "r"(a1), "r"(a2), "r"(a3), "r"(b0), "r"(b1));
}
__device__ __forceinline__ void ldsm4(uint32_t& r0, uint32_t& r1,
                                      uint32_t& r2, uint32_t& r3, uint32_t a) {
    asm volatile("ldmatrix.sync.aligned.m8n8.x4.shared.b16 {%0,%1,%2,%3}, [%4];"
                 : "=r"(r0), "=r"(r1), "=r"(r2), "=r"(r3) : "r"(a));
}
__device__ __forceinline__ void ldsm2t(uint32_t& r0, uint32_t& r1, uint32_t a) {
    asm volatile("ldmatrix.sync.aligned.m8n8.x2.trans.shared.b16 {%0,%1}, [%2];"
                 : "=r"(r0), "=r"(r1) : "r"(a));
}
__device__ __forceinline__ uint32_t h2u(__half2 h) { return *(uint32_t*)&h; }
__device__ __forceinline__ __half2 u2h(uint32_t u) { return *(__half2*)&u; }

// ==============================================================================
// Prepass: round x / qkv_w / proj_w to tf32 into scratch copies.
// ==============================================================================
__global__ __launch_bounds__(256) void tf32_prep(const float* __restrict__ x,
                                                 const float* __restrict__ wq,
                                                 const float* __restrict__ wp)
{
    const float4* src; float4* dst; int n4;
    if (blockIdx.y == 0)      { src = (const float4*)x;  dst = (float4*)g_xr;  n4 = 524288; }
    else if (blockIdx.y == 1) { src = (const float4*)wq; dst = (float4*)g_wqr; n4 = 786432; }
    else                      { src = (const float4*)wp; dst = (float4*)g_wpr; n4 = 262144; }
    int i = blockIdx.x * 256 + threadIdx.x;
    if (i < n4) {
        float4 v = src[i];
        v.x = __uint_as_float(f2tf32(v.x));
        v.y = __uint_as_float(f2tf32(v.y));
        v.z = __uint_as_float(f2tf32(v.z));
        v.w = __uint_as_float(f2tf32(v.w));
        dst[i] = v;
    }
}

// ==============================================================================
// Tensor-core tf32 GEMM (NT): C[m,n] = sum_k A[m,k]*B[n,k] + bias[n]
// Inputs pre-rounded to tf32 -> no CVT in inner loop. (proven round-5 kernel)
// ==============================================================================
#define GEMM_SMEM (3*2*128*20*4)   // 61440 bytes

template<int MODE>
__global__ __launch_bounds__(256, 2) void mma_nt(
    const float* __restrict__ bias, float* __restrict__ C, int N, int K)
{
    constexpr int BK  = 16;
    constexpr int PAD = 20;
    extern __shared__ float smg[];
    float (*As)[128][PAD] = (float(*)[128][PAD])smg;
    float (*Bs)[128][PAD] = (float(*)[128][PAD])(smg + 3*128*PAD);

    const int tid  = threadIdx.x;
    const int warp = tid >> 5;
    const int lane = tid & 31;
    const int gr   = lane >> 2;
    const int tg   = lane & 3;
    const int wm   = (warp & 3) * 32;
    const int wn   = (warp >> 2) * 64;
    const int mb   = blockIdx.y * 128;
    const int nb   = blockIdx.x * 128;

    const float* Ap = (MODE == 0) ? &g_y[0][0] : g_xr;
    const float* Bp = (MODE == 0) ? g_wpr      : g_wqr;

    const int lrow = tid >> 2;
    const int lcol = (tid & 3) * 4;
    const float* aG = Ap + (size_t)(mb + lrow) * K + lcol;
    const float* bG = Bp + (size_t)(nb + lrow) * K + lcol;

    float acc[2][8][4];
#pragma unroll
    for (int i = 0; i < 2; i++)
#pragma unroll
        for (int j = 0; j < 8; j++)
#pragma unroll
            for (int r = 0; r < 4; r++) acc[i][j][r] = 0.f;

    auto load_tiles = [&](int st, int k0) {
        cp16(smem_u32(&As[st][lrow     ][lcol]), aG + k0);
        cp16(smem_u32(&As[st][lrow + 64][lcol]), aG + (size_t)64 * K + k0);
        cp16(smem_u32(&Bs[st][lrow     ][lcol]), bG + k0);
        cp16(smem_u32(&Bs[st][lrow + 64][lcol]), bG + (size_t)64 * K + k0);
        asm volatile("cp.async.commit_group;\n");
    };

    const int nK = K / BK;
    load_tiles(0, 0);
    load_tiles(1, BK);

    for (int kt = 0; kt < nK; kt++) {
        asm volatile("cp.async.wait_group 1;\n");
        __syncthreads();
        if (kt + 2 < nK) load_tiles((kt + 2) % 3, (kt + 2) * BK);
        const int buf = kt % 3;

#pragma unroll
        for (int ks = 0; ks < 2; ks++) {
            const int k0 = ks * 8;
            uint32_t af[2][4];
#pragma unroll
            for (int i = 0; i < 2; i++) {
                const int r = wm + i * 16;
                af[i][0] = __float_as_uint(As[buf][r + gr    ][k0 + tg    ]);
                af[i][1] = __float_as_uint(As[buf][r + gr + 8][k0 + tg    ]);
                af[i][2] = __float_as_uint(As[buf][r + gr    ][k0 + tg + 4]);
                af[i][3] = __float_as_uint(As[buf][r + gr + 8][k0 + tg + 4]);
            }
#pragma unroll
            for (int j = 0; j < 8; j++) {
                const int n = wn + j * 8;
                uint32_t b0 = __float_as_uint(Bs[buf][n + gr][k0 + tg    ]);
                uint32_t b1 = __float_as_uint(Bs[buf][n + gr][k0 + tg + 4]);
#pragma unroll
                for (int i = 0; i < 2; i++)
                    mma_tf32(acc[i][j], af[i][0], af[i][1], af[i][2], af[i][3],
                             b0, b1);
            }
        }
    }

#pragma unroll
    for (int i = 0; i < 2; i++) {
#pragma unroll
        for (int j = 0; j < 8; j++) {
            const int r0 = mb + wm + i * 16 + gr;
            const int c0 = nb + wn + j * 8 + 2 * tg;
            const float bia0 = bias[c0], bia1 = bias[c0 + 1];
            if (MODE == 1) {
#pragma unroll
                for (int e = 0; e < 4; e++) {
                    const int m = r0 + (e >> 1) * 8;
                    const int n = c0 + (e & 1);
                    const float v = acc[i][j][e] + ((e & 1) ? bia1 : bia0);
                    const int tsel = n >> 10, rem = n & 1023;
                    const int h = rem >> 6, d = rem & 63;
                    const int bb = m >> 10, s = m & 1023;
                    g_qkv[tsel][bb * NHEADS + h][s][d] = v;
                }
            } else {
                float2 lo = make_float2(acc[i][j][0] + bia0, acc[i][j][1] + bia1);
                float2 hi = make_float2(acc[i][j][2] + bia0, acc[i][j][3] + bia1);
                *(float2*)&C[(size_t)r0 * N + c0]        = lo;
                *(float2*)&C[(size_t)(r0 + 8) * N + c0]  = hi;
            }
        }
    }
}

// ==============================================================================
// Laplacian kernel, fp16 half2 distance math:
//   diff = HSUB2(q,k) [fma pipe], abs = AND 0x7FFF7FFF [alu pipe],
//   acc  = HADD2      [fma pipe]   -> 2 fma-pipe inst per 2 dims (rt=2 each).
// Two half2 accumulators (d2<16 / d2>=16), combined in fp32 -> exp -> fp16 store.
// Grid (16 i-tiles, 32 bh), 256 threads, 4x4 microtile.
// ==============================================================================
__global__ __launch_bounds__(256) void laplace_kern()
{
    __shared__ uint32_t qs[32][64];   // [d2][i] half2 (2 dims)
    __shared__ uint32_t ks[32][64];   // [d2][j] half2

    const int tid = threadIdx.x;
    const int tx  = tid & 15;
    const int ty  = tid >> 4;
    const int it  = blockIdx.x;
    const int bh  = blockIdx.y;

    const float* Q  = &g_qkv[0][bh][it*64][0];
    const float* Kp = &g_qkv[1][bh][0][0];

#pragma unroll
    for (int r = 0; r < 4; r++) {
        int idx = r*1024 + tid*4;
        int i = idx >> 6, d = idx & 63;
        float4 v = *(const float4*)(Q + i*64 + d);
        qs[(d>>1)    ][i] = h2u(__floats2half2_rn(v.x, v.y));
        qs[(d>>1) + 1][i] = h2u(__floats2half2_rn(v.z, v.w));
    }

    float rs[4] = {0.f, 0.f, 0.f, 0.f};
    char* kout = (char*)&g_kern_h[bh][it*64][0];

    for (int jt = 0; jt < 16; jt++) {
#pragma unroll
        for (int r = 0; r < 4; r++) {
            int idx = r*1024 + tid*4;
            int j = idx >> 6, d = idx & 63;
            float4 v = *(const float4*)(Kp + (jt*64 + j)*64 + d);
            ks[(d>>1)    ][j] = h2u(__floats2half2_rn(v.x, v.y));
            ks[(d>>1) + 1][j] = h2u(__floats2half2_rn(v.z, v.w));
        }
        __syncthreads();

        __half2 accA[4][4], accB[4][4];
#pragma unroll
        for (int ii = 0; ii < 4; ii++)
#pragma unroll
            for (int jj = 0; jj < 4; jj++) {
                accA[ii][jj] = __half2half2(__ushort_as_half(0));
                accB[ii][jj] = __half2half2(__ushort_as_half(0));
            }

#pragma unroll
        for (int d2 = 0; d2 < 32; d2++) {
            uint4 qv = *(const uint4*)&qs[d2][ty*4];
            uint4 kv = *(const uint4*)&ks[d2][tx*4];
            uint32_t q2[4] = {qv.x, qv.y, qv.z, qv.w};
            uint32_t k2[4] = {kv.x, kv.y, kv.z, kv.w};
#pragma unroll
            for (int ii = 0; ii < 4; ii++)
#pragma unroll
                for (int jj = 0; jj < 4; jj++) {
                    uint32_t df = h2u(__hsub2(u2h(q2[ii]), u2h(k2[jj])))
                                & 0x7FFF7FFFu;
                    if (d2 < 16) accA[ii][jj] = __hadd2(accA[ii][jj], u2h(df));
                    else         accB[ii][jj] = __hadd2(accB[ii][jj], u2h(df));
                }
        }

#pragma unroll
        for (int ii = 0; ii < 4; ii++) {
            float op[4];
#pragma unroll
            for (int jj = 0; jj < 4; jj++) {
                float2 fa = __half22float2(accA[ii][jj]);
                float2 fb = __half22float2(accB[ii][jj]);
                float dist = (fa.x + fa.y) + (fb.x + fb.y);
                float kv = __expf(-0.0625f * dist);
                op[jj] = kv;
                rs[ii] += kv;
            }
            __half2 p01 = __floats2half2_rn(op[0], op[1]);
            __half2 p23 = __floats2half2_rn(op[2], op[3]);
            *(uint2*)(kout + ((size_t)(ty*4 + ii)*1024 + jt*64 + tx*4)*2)
                = make_uint2(h2u(p01), h2u(p23));
        }
        __syncthreads();
    }

#pragma unroll
    for (int ii = 0; ii < 4; ii++) {
        float v = rs[ii];
        v += __shfl_xor_sync(0xffffffffu, v, 1);
        v += __shfl_xor_sync(0xffffffffu, v, 2);
        v += __shfl_xor_sync(0xffffffffu, v, 4);
        v += __shfl_xor_sync(0xffffffffu, v, 8);
        if (tx == 0) g_rowsum[bh][it*64 + ty*4 + ii] = v;
    }
}

// ==============================================================================
// attnv_tc: global = (kern_fp16 @ v) via m16n8k16 HMMA; v in fp16 hi/lo (2 mmas).
// + row normalize + depthwise conv + store g_y (tf32-rounded). (proven round-5)
// ==============================================================================
#define AV_STAGE 36864
#define AV_SMEM  (2*AV_STAGE)

__global__ __launch_bounds__(256, 2) void attnv_tc(const float* __restrict__ dwc_w,
                                                   const float* __restrict__ dwc_b)
{
    extern __shared__ char sm[];
    const int tid  = threadIdx.x;
    const int warp = tid >> 5;
    const int lane = tid & 31;
    const int gr   = lane >> 2;
    const int tg   = lane & 3;
    const int it   = blockIdx.x;
    const int bh   = blockIdx.y;
    const int bb   = bh >> 4;
    const int h    = bh & 15;

    const __half* Kh = &g_kern_h[bh][0][0];
    const float*  V  = &g_qkv[2][bh][0][0];
    const uint32_t smBase = smem_u32(sm);

    float acc[8][4];
#pragma unroll
    for (int n = 0; n < 8; n++)
#pragma unroll
        for (int e = 0; e < 4; e++) acc[n][e] = 0.f;

    const int arow = tid >> 3, achk = tid & 7;
    const int vrow = tid >> 4, vd = (tid & 15) * 4;

    auto issue_kern = [&](int st, int k0) {
        const uint32_t dst = smBase + st * AV_STAGE;
#pragma unroll
        for (int q = 0; q < 4; q++) {
            int r = arow + 32 * q;
            cp16(dst + r * 144 + achk * 16,
                 Kh + (size_t)(it * 128 + r) * 1024 + k0 + achk * 8);
        }
        asm volatile("cp.async.commit_group;\n");
    };
    auto ldg_v = [&](int k0, float4* vr) {
#pragma unroll
        for (int q = 0; q < 4; q++)
            vr[q] = *(const float4*)(V + (size_t)(k0 + vrow + 16 * q) * 64 + vd);
    };
    auto sts_v = [&](int st, const float4* vr) {
        char* vhB = sm + st * AV_STAGE + 18432;
        char* vlB = sm + st * AV_STAGE + 27648;
#pragma unroll
        for (int q = 0; q < 4; q++) {
            int r = vrow + 16 * q;
            float4 vv = vr[q];
            __half hx = __float2half_rn(vv.x), hy = __float2half_rn(vv.y);
            __half hz = __float2half_rn(vv.z), hw = __float2half_rn(vv.w);
            __half2 hi0 = __halves2half2(hx, hy), hi1 = __halves2half2(hz, hw);
            __half2 lo0 = __floats2half2_rn(vv.x - __half2float(hx),
                                            vv.y - __half2float(hy));
            __half2 lo1 = __floats2half2_rn(vv.z - __half2float(hz),
                                            vv.w - __half2float(hw));
            *(uint2*)(vhB + r * 144 + vd * 2) = make_uint2(h2u(hi0), h2u(hi1));
            *(uint2*)(vlB + r * 144 + vd * 2) = make_uint2(h2u(lo0), h2u(lo1));
        }
    };

    const uint32_t aOff = (uint32_t)((warp * 16 + (lane & 7) + ((lane >> 3) & 1) * 8) * 144
                                     + (lane >> 4) * 16);
    const uint32_t bRow = (uint32_t)((lane & 15) * 144);

    issue_kern(0, 0);
    {
        float4 vr[4];
        ldg_v(0, vr);
        sts_v(0, vr);
    }

    for (int kt = 0; kt < 16; kt++) {
        const int cur = kt & 1;
        asm volatile("cp.async.wait_group 0;\n");
        __syncthreads();

        float4 vr[4];
        if (kt < 15) {
            issue_kern(cur ^ 1, (kt + 1) * 64);
            ldg_v((kt + 1) * 64, vr);
        }

        const uint32_t aB  = smBase + cur * AV_STAGE + aOff;
        const uint32_t vhB = smBase + cur * AV_STAGE + 18432 + bRow;
        const uint32_t vlB = smBase + cur * AV_STAGE + 27648 + bRow;
#pragma unroll
        for (int k16 = 0; k16 < 4; k16++) {
            uint32_t a0, a1, a2, a3;
            ldsm4(a0, a1, a2, a3, aB + k16 * 32);
#pragma unroll
            for (int nf = 0; nf < 8; nf++) {
                uint32_t bh0, bh1, bl0, bl1;
                ldsm2t(bh0, bh1, vhB + k16 * 2304 + nf * 16);
                ldsm2t(bl0, bl1, vlB + k16 * 2304 + nf * 16);
                mma_f16(acc[nf], a0, a1, a2, a3, bh0, bh1);
                mma_f16(acc[nf], a0, a1, a2, a3, bl0, bl1);
            }
        }

        if (kt < 15) sts_v(cur ^ 1, vr);
    }

    const int m0 = it * 128 + warp * 16 + gr;
#pragma unroll
    for (int nf = 0; nf < 8; nf++) {
        const int dl = nf * 8 + tg * 2;
        const int c  = h * 64 + dl;
        const float w0a = dwc_w[c*3+0], w1a = dwc_w[c*3+1], w2a = dwc_w[c*3+2];
        const float b0a = dwc_b[c];
        const float w0b = dwc_w[c*3+3], w1b = dwc_w[c*3+4], w2b = dwc_w[c*3+5];
        const float b1b = dwc_b[c+1];
#pragma unroll
        for (int half = 0; half < 2; half++) {
            const int s = m0 + half * 8;
            const float sc = 1.0f / (g_rowsum[bh][s] + 1e-6f);
            float o0 = acc[nf][half*2 + 0] * sc;
            float o1 = acc[nf][half*2 + 1] * sc;
            float2 v0 = *(const float2*)&V[(size_t)s*64 + dl];
            float2 vm = (s > 0)       ? *(const float2*)&V[(size_t)(s-1)*64 + dl]
                                      : make_float2(0.f, 0.f);
            float2 vp = (s < SEQ - 1) ? *(const float2*)&V[(size_t)(s+1)*64 + dl]
                                      : make_float2(0.f, 0.f);
            o0 += w0a*vm.x + w1a*v0.x + w2a*vp.x + b0a;
            o1 += w0b*vm.y + w1b*v0.y + w2b*vp.y + b1b;
            o0 = __uint_as_float(f2tf32(o0));
            o1 = __uint_as_float(f2tf32(o1));
            *(float2*)&g_y[bb*SEQ + s][c] = make_float2(o0, o1);
        }
    }
}

// ==============================================================================
extern "C" void kernel_launch(void* const* d_in, const int* in_sizes, int n_in,
                              void* d_out, int out_size)
{
    const float* x      = (const float*)d_in[0];
    const float* qkv_w  = (const float*)d_in[1];
    const float* qkv_b  = (const float*)d_in[2];
    const float* proj_w = (const float*)d_in[3];
    const float* proj_b = (const float*)d_in[4];
    const float* dwc_w  = (const float*)d_in[5];
    const float* dwc_b  = (const float*)d_in[6];
    float* out = (float*)d_out;

    cudaFuncSetAttribute(mma_nt<1>, cudaFuncAttributeMaxDynamicSharedMemorySize, GEMM_SMEM);
    cudaFuncSetAttribute(mma_nt<0>, cudaFuncAttributeMaxDynamicSharedMemorySize, GEMM_SMEM);
    cudaFuncSetAttribute(attnv_tc,  cudaFuncAttributeMaxDynamicSharedMemorySize, AV_SMEM);

    // 0) round x / weights to tf32 scratch copies
    tf32_prep<<<dim3(3072, 3), 256>>>(x, qkv_w, proj_w);
    // 1) qkv projection (tf32 HMMA), scatter to q/k/v
    mma_nt<1><<<dim3(24, 16), 256, GEMM_SMEM>>>(qkv_b, nullptr, 3072, 1024);
    // 2) Laplacian L1 kernel matrix (fp16 half2 math) + fp32 row sums
    laplace_kern<<<dim3(16, 32), 256>>>();
    // 3) kern_fp16 @ v (fp16 HMMA, v hi/lo) + normalize + dwc -> g_y (tf32)
    attnv_tc<<<dim3(8, 32), 256, AV_SMEM>>>(dwc_w, dwc_b);
    // 4) output projection (tf32 HMMA) -> d_out
    mma_nt<0><<<dim3(8, 16), 256, GEMM_SMEM>>>(proj_b, out, 1024, 1024);
}

// round 8
// speedup vs baseline: 1.6689x; 1.1919x over previous
#include <cuda_runtime.h>
#include <cuda_fp16.h>
#include <cstdint>

#define SEQ 1024
#define DIMC 1024
#define NHEADS 16
#define HDIM 64
#define NBATCH 2
#define NBH (NBATCH*NHEADS)   // 32

// ---------------- scratch (device globals; no runtime allocation) -------------
__device__ float  g_qkv[3][NBH][SEQ][HDIM];    // 24 MB  q/k/v [bh][s][d]
__device__ __half g_kern_h[NBH][SEQ][SEQ];     // 67 MB  fp16 kernel matrix
__device__ float  g_rowsum[NBH][SEQ];          // row sums (fp32)
__device__ __half g_xh[2048*1024];             // fp16 x
__device__ __half g_wqh[3072*1024];            // fp16 qkv_w
__device__ __half g_wph[1024*1024];            // fp16 proj_w
__device__ __half g_yh[2048*1024];             // fp16 pre-projection activations

// ---------------- helpers ------------------------------------------------------
__device__ __forceinline__ uint32_t smem_u32(const void* p) {
    return (uint32_t)__cvta_generic_to_shared(p);
}
__device__ __forceinline__ void cp16(uint32_t s, const void* g) {
    asm volatile("cp.async.cg.shared.global [%0], [%1], 16;\n" :: "r"(s), "l"(g));
}
__device__ __forceinline__ void mma_f16(float c[4],
        uint32_t a0, uint32_t a1, uint32_t a2, uint32_t a3,
        uint32_t b0, uint32_t b1) {
    asm volatile(
        "mma.sync.aligned.m16n8k16.row.col.f32.f16.f16.f32 "
        "{%0,%1,%2,%3}, {%4,%5,%6,%7}, {%8,%9}, {%0,%1,%2,%3};"
        : "+f"(c[0]), "+f"(c[1]), "+f"(c[2]), "+f"(c[3])
        : "r"(a0), "r"(a1), "r"(a2), "r"(a3), "r"(b0), "r"(b1));
}
__device__ __forceinline__ void ldsm4(uint32_t& r0, uint32_t& r1,
                                      uint32_t& r2, uint32_t& r3, uint32_t a) {
    asm volatile("ldmatrix.sync.aligned.m8n8.x4.shared.b16 {%0,%1,%2,%3}, [%4];"
                 : "=r"(r0), "=r"(r1), "=r"(r2), "=r"(r3) : "r"(a));
}
__device__ __forceinline__ void ldsm2t(uint32_t& r0, uint32_t& r1, uint32_t a) {
    asm volatile("ldmatrix.sync.aligned.m8n8.x2.trans.shared.b16 {%0,%1}, [%2];"
                 : "=r"(r0), "=r"(r1) : "r"(a));
}
__device__ __forceinline__ uint32_t h2u(__half2 h) { return *(uint32_t*)&h; }
__device__ __forceinline__ __half2 u2h(uint32_t u) { return *(__half2*)&u; }

// ==============================================================================
// Prepass: convert x / qkv_w / proj_w to fp16 scratch copies.
// ==============================================================================
__global__ __launch_bounds__(256) void prep_f16(const float* __restrict__ x,
                                                const float* __restrict__ wq,
                                                const float* __restrict__ wp)
{
    const float4* src; __half* dh; int n4;
    if (blockIdx.y == 0)      { src = (const float4*)x;  dh = g_xh;  n4 = 524288; }
    else if (blockIdx.y == 1) { src = (const float4*)wq; dh = g_wqh; n4 = 786432; }
    else                      { src = (const float4*)wp; dh = g_wph; n4 = 262144; }
    int i = blockIdx.x * 256 + threadIdx.x;
    if (i < n4) {
        float4 v = src[i];
        ((uint2*)dh)[i] = make_uint2(h2u(__floats2half2_rn(v.x, v.y)),
                                     h2u(__floats2half2_rn(v.z, v.w)));
    }
}

// ==============================================================================
// Plain fp16 tensor-core GEMM (NT): C = A @ B^T + bias, fp32 accumulate.
// BM=BN=128, BK=32, 256 thr / 8 warps (4Mx2N), warptile 32x64, 2-stage cp.async.
// MODE 1: A=x, B=qkv_w, scatter to g_qkv.  MODE 0: A=y, B=proj_w, row-major C.
// smem stage: A | B, each 128 rows x 40 halves (80 B stride).
// ==============================================================================
#define HG_STAGE 20480
#define HG_SMEM  (2*HG_STAGE)

template<int MODE>
__global__ __launch_bounds__(256, 2) void hgemm_nt(
    const float* __restrict__ bias, float* __restrict__ C, int N, int K)
{
    extern __shared__ char smh[];
    const uint32_t smB = smem_u32(smh);

    const int tid  = threadIdx.x;
    const int warp = tid >> 5;
    const int lane = tid & 31;
    const int gr   = lane >> 2;
    const int tg   = lane & 3;
    const int wm   = (warp & 3) * 32;
    const int wn   = (warp >> 2) * 64;
    const int mb   = blockIdx.y * 128;
    const int nb   = blockIdx.x * 128;

    const __half* AH = (MODE == 1) ? g_xh  : g_yh;
    const __half* BH = (MODE == 1) ? g_wqh : g_wph;

    const int row = tid >> 1;
    const int cp  = (tid & 1) * 2;
    const __half* aHg = AH + (size_t)(mb + row) * K + cp * 8;
    const __half* bHg = BH + (size_t)(nb + row) * K + cp * 8;
    const uint32_t stDst = row * 80 + cp * 16;

    auto load_st = [&](int st, int k0) {
        const uint32_t d = smB + st * HG_STAGE + stDst;
        cp16(d,         aHg + k0); cp16(d + 16,         aHg + k0 + 8);
        cp16(d + 10240, bHg + k0); cp16(d + 10240 + 16, bHg + k0 + 8);
        asm volatile("cp.async.commit_group;\n");
    };

    float acc[2][8][4];
#pragma unroll
    for (int i = 0; i < 2; i++)
#pragma unroll
        for (int j = 0; j < 8; j++)
#pragma unroll
            for (int r = 0; r < 4; r++) acc[i][j][r] = 0.f;

    const uint32_t aOff = (wm + (lane & 15)) * 80 + (lane >> 4) * 16;
    const uint32_t bOff = (wn + (lane & 15)) * 80 + (lane >> 4) * 16 + 10240;

    const int nK = K / 32;
    load_st(0, 0);

    for (int kt = 0; kt < nK; kt++) {
        asm volatile("cp.async.wait_group 0;\n");
        __syncthreads();
        if (kt + 1 < nK) load_st((kt + 1) & 1, (kt + 1) * 32);
        const uint32_t sb = smB + (kt & 1) * HG_STAGE;

#pragma unroll
        for (int s = 0; s < 2; s++) {
            uint32_t ah[2][4];
#pragma unroll
            for (int i = 0; i < 2; i++)
                ldsm4(ah[i][0], ah[i][1], ah[i][2], ah[i][3],
                      sb + aOff + i * 1280 + s * 32);
#pragma unroll
            for (int j = 0; j < 4; j++) {
                uint32_t bh_[4];
                ldsm4(bh_[0], bh_[1], bh_[2], bh_[3],
                      sb + bOff + j * 1280 + s * 32);
#pragma unroll
                for (int i = 0; i < 2; i++) {
                    mma_f16(acc[i][2*j  ], ah[i][0], ah[i][1], ah[i][2], ah[i][3], bh_[0], bh_[2]);
                    mma_f16(acc[i][2*j+1], ah[i][0], ah[i][1], ah[i][2], ah[i][3], bh_[1], bh_[3]);
                }
            }
        }
    }

    // epilogue (m16n8 fragment layout)
#pragma unroll
    for (int i = 0; i < 2; i++) {
#pragma unroll
        for (int j = 0; j < 8; j++) {
            const int r0 = mb + wm + i * 16 + gr;
            const int c0 = nb + wn + j * 8 + 2 * tg;
            const float bia0 = bias[c0], bia1 = bias[c0 + 1];
            if (MODE == 1) {
#pragma unroll
                for (int e = 0; e < 4; e++) {
                    const int m = r0 + (e >> 1) * 8;
                    const int n = c0 + (e & 1);
                    const float v = acc[i][j][e] + ((e & 1) ? bia1 : bia0);
                    const int tsel = n >> 10, rem = n & 1023;
                    const int h = rem >> 6, d = rem & 63;
                    const int bb = m >> 10, s = m & 1023;
                    g_qkv[tsel][bb * NHEADS + h][s][d] = v;
                }
            } else {
                float2 lo = make_float2(acc[i][j][0] + bia0, acc[i][j][1] + bia1);
                float2 hi = make_float2(acc[i][j][2] + bia0, acc[i][j][3] + bia1);
                *(float2*)&C[(size_t)r0 * N + c0]       = lo;
                *(float2*)&C[(size_t)(r0 + 8) * N + c0] = hi;
            }
        }
    }
}

// ==============================================================================
// Laplacian kernel, fp16 half2 distance math (proven round-7).
// ==============================================================================
__global__ __launch_bounds__(256) void laplace_kern()
{
    __shared__ uint32_t qs[32][64];   // [d2][i] half2
    __shared__ uint32_t ks[32][64];   // [d2][j] half2

    const int tid = threadIdx.x;
    const int tx  = tid & 15;
    const int ty  = tid >> 4;
    const int it  = blockIdx.x;
    const int bh  = blockIdx.y;

    const float* Q  = &g_qkv[0][bh][it*64][0];
    const float* Kp = &g_qkv[1][bh][0][0];

#pragma unroll
    for (int r = 0; r < 4; r++) {
        int idx = r*1024 + tid*4;
        int i = idx >> 6, d = idx & 63;
        float4 v = *(const float4*)(Q + i*64 + d);
        qs[(d>>1)    ][i] = h2u(__floats2half2_rn(v.x, v.y));
        qs[(d>>1) + 1][i] = h2u(__floats2half2_rn(v.z, v.w));
    }

    float rs[4] = {0.f, 0.f, 0.f, 0.f};
    char* kout = (char*)&g_kern_h[bh][it*64][0];

    for (int jt = 0; jt < 16; jt++) {
#pragma unroll
        for (int r = 0; r < 4; r++) {
            int idx = r*1024 + tid*4;
            int j = idx >> 6, d = idx & 63;
            float4 v = *(const float4*)(Kp + (jt*64 + j)*64 + d);
            ks[(d>>1)    ][j] = h2u(__floats2half2_rn(v.x, v.y));
            ks[(d>>1) + 1][j] = h2u(__floats2half2_rn(v.z, v.w));
        }
        __syncthreads();

        __half2 accA[4][4], accB[4][4];
#pragma unroll
        for (int ii = 0; ii < 4; ii++)
#pragma unroll
            for (int jj = 0; jj < 4; jj++) {
                accA[ii][jj] = __half2half2(__ushort_as_half(0));
                accB[ii][jj] = __half2half2(__ushort_as_half(0));
            }

#pragma unroll
        for (int d2 = 0; d2 < 32; d2++) {
            uint4 qv = *(const uint4*)&qs[d2][ty*4];
            uint4 kv = *(const uint4*)&ks[d2][tx*4];
            uint32_t q2[4] = {qv.x, qv.y, qv.z, qv.w};
            uint32_t k2[4] = {kv.x, kv.y, kv.z, kv.w};
#pragma unroll
            for (int ii = 0; ii < 4; ii++)
#pragma unroll
                for (int jj = 0; jj < 4; jj++) {
                    uint32_t df = h2u(__hsub2(u2h(q2[ii]), u2h(k2[jj])))
                                & 0x7FFF7FFFu;
                    if (d2 < 16) accA[ii][jj] = __hadd2(accA[ii][jj], u2h(df));
                    else         accB[ii][jj] = __hadd2(accB[ii][jj], u2h(df));
                }
        }

#pragma unroll
        for (int ii = 0; ii < 4; ii++) {
            float op[4];
#pragma unroll
            for (int jj = 0; jj < 4; jj++) {
                float2 fa = __half22float2(accA[ii][jj]);
                float2 fb = __half22float2(accB[ii][jj]);
                float dist = (fa.x + fa.y) + (fb.x + fb.y);
                float kv = __expf(-0.0625f * dist);
                op[jj] = kv;
                rs[ii] += kv;
            }
            __half2 p01 = __floats2half2_rn(op[0], op[1]);
            __half2 p23 = __floats2half2_rn(op[2], op[3]);
            *(uint2*)(kout + ((size_t)(ty*4 + ii)*1024 + jt*64 + tx*4)*2)
                = make_uint2(h2u(p01), h2u(p23));
        }
        __syncthreads();
    }

#pragma unroll
    for (int ii = 0; ii < 4; ii++) {
        float v = rs[ii];
        v += __shfl_xor_sync(0xffffffffu, v, 1);
        v += __shfl_xor_sync(0xffffffffu, v, 2);
        v += __shfl_xor_sync(0xffffffffu, v, 4);
        v += __shfl_xor_sync(0xffffffffu, v, 8);
        if (tx == 0) g_rowsum[bh][it*64 + ty*4 + ii] = v;
    }
}

// ==============================================================================
// attnv_tc: global = (kern_fp16 @ v) via m16n8k16 HMMA; v fp16 hi/lo (2 mmas).
// + row normalize + depthwise conv; y emitted as fp16 (g_yh).
// ==============================================================================
#define AV_STAGE 36864
#define AV_SMEM  (2*AV_STAGE)

__global__ __launch_bounds__(256, 2) void attnv_tc(const float* __restrict__ dwc_w,
                                                   const float* __restrict__ dwc_b)
{
    extern __shared__ char sm[];
    const int tid  = threadIdx.x;
    const int warp = tid >> 5;
    const int lane = tid & 31;
    const int gr   = lane >> 2;
    const int tg   = lane & 3;
    const int it   = blockIdx.x;
    const int bh   = blockIdx.y;
    const int bb   = bh >> 4;
    const int h    = bh & 15;

    const __half* Kh = &g_kern_h[bh][0][0];
    const float*  V  = &g_qkv[2][bh][0][0];
    const uint32_t smBase = smem_u32(sm);

    float acc[8][4];
#pragma unroll
    for (int n = 0; n < 8; n++)
#pragma unroll
        for (int e = 0; e < 4; e++) acc[n][e] = 0.f;

    const int arow = tid >> 3, achk = tid & 7;
    const int vrow = tid >> 4, vd = (tid & 15) * 4;

    auto issue_kern = [&](int st, int k0) {
        const uint32_t dst = smBase + st * AV_STAGE;
#pragma unroll
        for (int q = 0; q < 4; q++) {
            int r = arow + 32 * q;
            cp16(dst + r * 144 + achk * 16,
                 Kh + (size_t)(it * 128 + r) * 1024 + k0 + achk * 8);
        }
        asm volatile("cp.async.commit_group;\n");
    };
    auto ldg_v = [&](int k0, float4* vr) {
#pragma unroll
        for (int q = 0; q < 4; q++)
            vr[q] = *(const float4*)(V + (size_t)(k0 + vrow + 16 * q) * 64 + vd);
    };
    auto sts_v = [&](int st, const float4* vr) {
        char* vhB = sm + st * AV_STAGE + 18432;
        char* vlB = sm + st * AV_STAGE + 27648;
#pragma unroll
        for (int q = 0; q < 4; q++) {
            int r = vrow + 16 * q;
            float4 vv = vr[q];
            __half hx = __float2half_rn(vv.x), hy = __float2half_rn(vv.y);
            __half hz = __float2half_rn(vv.z), hw = __float2half_rn(vv.w);
            __half2 hi0 = __halves2half2(hx, hy), hi1 = __halves2half2(hz, hw);
            __half2 lo0 = __floats2half2_rn(vv.x - __half2float(hx),
                                            vv.y - __half2float(hy));
            __half2 lo1 = __floats2half2_rn(vv.z - __half2float(hz),
                                            vv.w - __half2float(hw));
            *(uint2*)(vhB + r * 144 + vd * 2) = make_uint2(h2u(hi0), h2u(hi1));
            *(uint2*)(vlB + r * 144 + vd * 2) = make_uint2(h2u(lo0), h2u(lo1));
        }
    };

    const uint32_t aOff = (uint32_t)((warp * 16 + (lane & 7) + ((lane >> 3) & 1) * 8) * 144
                                     + (lane >> 4) * 16);
    const uint32_t bRow = (uint32_t)((lane & 15) * 144);

    issue_kern(0, 0);
    {
        float4 vr[4];
        ldg_v(0, vr);
        sts_v(0, vr);
    }

    for (int kt = 0; kt < 16; kt++) {
        const int cur = kt & 1;
        asm volatile("cp.async.wait_group 0;\n");
        __syncthreads();

        float4 vr[4];
        if (kt < 15) {
            issue_kern(cur ^ 1, (kt + 1) * 64);
            ldg_v((kt + 1) * 64, vr);
        }

        const uint32_t aB  = smBase + cur * AV_STAGE + aOff;
        const uint32_t vhB = smBase + cur * AV_STAGE + 18432 + bRow;
        const uint32_t vlB = smBase + cur * AV_STAGE + 27648 + bRow;
#pragma unroll
        for (int k16 = 0; k16 < 4; k16++) {
            uint32_t a0, a1, a2, a3;
            ldsm4(a0, a1, a2, a3, aB + k16 * 32);
#pragma unroll
            for (int nf = 0; nf < 8; nf++) {
                uint32_t bh0, bh1, bl0, bl1;
                ldsm2t(bh0, bh1, vhB + k16 * 2304 + nf * 16);
                ldsm2t(bl0, bl1, vlB + k16 * 2304 + nf * 16);
                mma_f16(acc[nf], a0, a1, a2, a3, bh0, bh1);
                mma_f16(acc[nf], a0, a1, a2, a3, bl0, bl1);
            }
        }

        if (kt < 15) sts_v(cur ^ 1, vr);
    }

    // ---- epilogue: normalize + depthwise conv; emit y as fp16 ----
    const int m0 = it * 128 + warp * 16 + gr;
#pragma unroll
    for (int nf = 0; nf < 8; nf++) {
        const int dl = nf * 8 + tg * 2;
        const int c  = h * 64 + dl;
        const float w0a = dwc_w[c*3+0], w1a = dwc_w[c*3+1], w2a = dwc_w[c*3+2];
        const float b0a = dwc_b[c];
        const float w0b = dwc_w[c*3+3], w1b = dwc_w[c*3+4], w2b = dwc_w[c*3+5];
        const float b1b = dwc_b[c+1];
#pragma unroll
        for (int half = 0; half < 2; half++) {
            const int s = m0 + half * 8;
            const float sc = 1.0f / (g_rowsum[bh][s] + 1e-6f);
            float o0 = acc[nf][half*2 + 0] * sc;
            float o1 = acc[nf][half*2 + 1] * sc;
            float2 v0 = *(const float2*)&V[(size_t)s*64 + dl];
            float2 vm = (s > 0)       ? *(const float2*)&V[(size_t)(s-1)*64 + dl]
                                      : make_float2(0.f, 0.f);
            float2 vp = (s < SEQ - 1) ? *(const float2*)&V[(size_t)(s+1)*64 + dl]
                                      : make_float2(0.f, 0.f);
            o0 += w0a*vm.x + w1a*v0.x + w2a*vp.x + b0a;
            o1 += w0b*vm.y + w1b*v0.y + w2b*vp.y + b1b;
            const size_t oidx = (size_t)(bb*SEQ + s) * 1024 + c;
            *(uint32_t*)&g_yh[oidx] = h2u(__floats2half2_rn(o0, o1));
        }
    }
}

// ==============================================================================
extern "C" void kernel_launch(void* const* d_in, const int* in_sizes, int n_in,
                              void* d_out, int out_size)
{
    const float* x      = (const float*)d_in[0];
    const float* qkv_w  = (const float*)d_in[1];
    const float* qkv_b  = (const float*)d_in[2];
    const float* proj_w = (const float*)d_in[3];
    const float* proj_b = (const float*)d_in[4];
    const float* dwc_w  = (const float*)d_in[5];
    const float* dwc_b  = (const float*)d_in[6];
    float* out = (float*)d_out;

    cudaFuncSetAttribute(hgemm_nt<1>, cudaFuncAttributeMaxDynamicSharedMemorySize, HG_SMEM);
    cudaFuncSetAttribute(hgemm_nt<0>, cudaFuncAttributeMaxDynamicSharedMemorySize, HG_SMEM);
    cudaFuncSetAttribute(attnv_tc,    cudaFuncAttributeMaxDynamicSharedMemorySize, AV_SMEM);

    // 0) convert x / weights to fp16 scratch
    prep_f16<<<dim3(3072, 3), 256>>>(x, qkv_w, proj_w);
    // 1) qkv projection (plain fp16 HMMA), scatter to q/k/v (fp32)
    hgemm_nt<1><<<dim3(24, 16), 256, HG_SMEM>>>(qkv_b, nullptr, 3072, 1024);
    // 2) Laplacian L1 kernel matrix (fp16 half2 math) + fp32 row sums
    laplace_kern<<<dim3(16, 32), 256>>>();
    // 3) kern_fp16 @ v (fp16 HMMA, v hi/lo) + normalize + dwc -> y (fp16)
    attnv_tc<<<dim3(8, 32), 256, AV_SMEM>>>(dwc_w, dwc_b);
    // 4) output projection (plain fp16 HMMA) -> d_out
    hgemm_nt<0><<<dim3(8, 16), 256, HG_SMEM>>>(proj_b, out, 1024, 1024);
}

// round 9
// speedup vs baseline: 1.6792x; 1.0062x over previous
#include <cuda_runtime.h>
#include <cuda_fp16.h>
#include <cstdint>

#define SEQ 1024
#define DIMC 1024
#define NHEADS 16
#define HDIM 64
#define NBATCH 2
#define NBH (NBATCH*NHEADS)   // 32

// ---------------- scratch (device globals; no runtime allocation) -------------
__device__ float  g_qkv[3][NBH][SEQ][HDIM];    // 24 MB  q/k/v [bh][s][d]
__device__ __half g_kern_h[NBH][SEQ][SEQ];     // 67 MB  fp16 kernel matrix
__device__ float  g_rowsum[NBH][SEQ];          // row sums (fp32)
__device__ __half g_xh[2048*1024];             // fp16 x
__device__ __half g_wqh[3072*1024];            // fp16 qkv_w
__device__ __half g_wph[1024*1024];            // fp16 proj_w
__device__ __half g_yh[2048*1024];             // fp16 pre-projection activations

// ---------------- helpers ------------------------------------------------------
__device__ __forceinline__ uint32_t smem_u32(const void* p) {
    return (uint32_t)__cvta_generic_to_shared(p);
}
__device__ __forceinline__ void cp16(uint32_t s, const void* g) {
    asm volatile("cp.async.cg.shared.global [%0], [%1], 16;\n" :: "r"(s), "l"(g));
}
__device__ __forceinline__ void mma_f16(float c[4],
        uint32_t a0, uint32_t a1, uint32_t a2, uint32_t a3,
        uint32_t b0, uint32_t b1) {
    asm volatile(
        "mma.sync.aligned.m16n8k16.row.col.f32.f16.f16.f32 "
        "{%0,%1,%2,%3}, {%4,%5,%6,%7}, {%8,%9}, {%0,%1,%2,%3};"
        : "+f"(c[0]), "+f"(c[1]), "+f"(c[2]), "+f"(c[3])
        : "r"(a0), "r"(a1), "r"(a2), "r"(a3), "r"(b0), "r"(b1));
}
__device__ __forceinline__ void ldsm4(uint32_t& r0, uint32_t& r1,
                                      uint32_t& r2, uint32_t& r3, uint32_t a) {
    asm volatile("ldmatrix.sync.aligned.m8n8.x4.shared.b16 {%0,%1,%2,%3}, [%4];"
                 : "=r"(r0), "=r"(r1), "=r"(r2), "=r"(r3) : "r"(a));
}
__device__ __forceinline__ void ldsm2t(uint32_t& r0, uint32_t& r1, uint32_t a) {
    asm volatile("ldmatrix.sync.aligned.m8n8.x2.trans.shared.b16 {%0,%1}, [%2];"
                 : "=r"(r0), "=r"(r1) : "r"(a));
}
__device__ __forceinline__ uint32_t h2u(__half2 h) { return *(uint32_t*)&h; }
__device__ __forceinline__ __half2 u2h(uint32_t u) { return *(__half2*)&u; }

// ==============================================================================
// Prepass: convert x / qkv_w / proj_w to fp16 scratch copies.
// ==============================================================================
__global__ __launch_bounds__(256) void prep_f16(const float* __restrict__ x,
                                                const float* __restrict__ wq,
                                                const float* __restrict__ wp)
{
    const float4* src; __half* dh; int n4;
    if (blockIdx.y == 0)      { src = (const float4*)x;  dh = g_xh;  n4 = 524288; }
    else if (blockIdx.y == 1) { src = (const float4*)wq; dh = g_wqh; n4 = 786432; }
    else                      { src = (const float4*)wp; dh = g_wph; n4 = 262144; }
    int i = blockIdx.x * 256 + threadIdx.x;
    if (i < n4) {
        float4 v = src[i];
        ((uint2*)dh)[i] = make_uint2(h2u(__floats2half2_rn(v.x, v.y)),
                                     h2u(__floats2half2_rn(v.z, v.w)));
    }
}

// ==============================================================================
// Plain fp16 tensor-core GEMM (NT): C = A @ B^T + bias, fp32 accumulate.
// (proven round-8 kernel, unchanged)
// ==============================================================================
#define HG_STAGE 20480
#define HG_SMEM  (2*HG_STAGE)

template<int MODE>
__global__ __launch_bounds__(256, 2) void hgemm_nt(
    const float* __restrict__ bias, float* __restrict__ C, int N, int K)
{
    extern __shared__ char smh[];
    const uint32_t smB = smem_u32(smh);

    const int tid  = threadIdx.x;
    const int warp = tid >> 5;
    const int lane = tid & 31;
    const int gr   = lane >> 2;
    const int tg   = lane & 3;
    const int wm   = (warp & 3) * 32;
    const int wn   = (warp >> 2) * 64;
    const int mb   = blockIdx.y * 128;
    const int nb   = blockIdx.x * 128;

    const __half* AH = (MODE == 1) ? g_xh  : g_yh;
    const __half* BH = (MODE == 1) ? g_wqh : g_wph;

    const int row = tid >> 1;
    const int cp  = (tid & 1) * 2;
    const __half* aHg = AH + (size_t)(mb + row) * K + cp * 8;
    const __half* bHg = BH + (size_t)(nb + row) * K + cp * 8;
    const uint32_t stDst = row * 80 + cp * 16;

    auto load_st = [&](int st, int k0) {
        const uint32_t d = smB + st * HG_STAGE + stDst;
        cp16(d,         aHg + k0); cp16(d + 16,         aHg + k0 + 8);
        cp16(d + 10240, bHg + k0); cp16(d + 10240 + 16, bHg + k0 + 8);
        asm volatile("cp.async.commit_group;\n");
    };

    float acc[2][8][4];
#pragma unroll
    for (int i = 0; i < 2; i++)
#pragma unroll
        for (int j = 0; j < 8; j++)
#pragma unroll
            for (int r = 0; r < 4; r++) acc[i][j][r] = 0.f;

    const uint32_t aOff = (wm + (lane & 15)) * 80 + (lane >> 4) * 16;
    const uint32_t bOff = (wn + (lane & 15)) * 80 + (lane >> 4) * 16 + 10240;

    const int nK = K / 32;
    load_st(0, 0);

    for (int kt = 0; kt < nK; kt++) {
        asm volatile("cp.async.wait_group 0;\n");
        __syncthreads();
        if (kt + 1 < nK) load_st((kt + 1) & 1, (kt + 1) * 32);
        const uint32_t sb = smB + (kt & 1) * HG_STAGE;

#pragma unroll
        for (int s = 0; s < 2; s++) {
            uint32_t ah[2][4];
#pragma unroll
            for (int i = 0; i < 2; i++)
                ldsm4(ah[i][0], ah[i][1], ah[i][2], ah[i][3],
                      sb + aOff + i * 1280 + s * 32);
#pragma unroll
            for (int j = 0; j < 4; j++) {
                uint32_t bh_[4];
                ldsm4(bh_[0], bh_[1], bh_[2], bh_[3],
                      sb + bOff + j * 1280 + s * 32);
#pragma unroll
                for (int i = 0; i < 2; i++) {
                    mma_f16(acc[i][2*j  ], ah[i][0], ah[i][1], ah[i][2], ah[i][3], bh_[0], bh_[2]);
                    mma_f16(acc[i][2*j+1], ah[i][0], ah[i][1], ah[i][2], ah[i][3], bh_[1], bh_[3]);
                }
            }
        }
    }

#pragma unroll
    for (int i = 0; i < 2; i++) {
#pragma unroll
        for (int j = 0; j < 8; j++) {
            const int r0 = mb + wm + i * 16 + gr;
            const int c0 = nb + wn + j * 8 + 2 * tg;
            const float bia0 = bias[c0], bia1 = bias[c0 + 1];
            if (MODE == 1) {
#pragma unroll
                for (int e = 0; e < 4; e++) {
                    const int m = r0 + (e >> 1) * 8;
                    const int n = c0 + (e & 1);
                    const float v = acc[i][j][e] + ((e & 1) ? bia1 : bia0);
                    const int tsel = n >> 10, rem = n & 1023;
                    const int h = rem >> 6, d = rem & 63;
                    const int bb = m >> 10, s = m & 1023;
                    g_qkv[tsel][bb * NHEADS + h][s][d] = v;
                }
            } else {
                float2 lo = make_float2(acc[i][j][0] + bia0, acc[i][j][1] + bia1);
                float2 hi = make_float2(acc[i][j][2] + bia0, acc[i][j][3] + bia1);
                *(float2*)&C[(size_t)r0 * N + c0]       = lo;
                *(float2*)&C[(size_t)(r0 + 8) * N + c0] = hi;
            }
        }
    }
}

// ==============================================================================
// Laplacian kernel, fp16 half2 distance math.
// Single half2 accumulator + __habs2 folded into HADD2; 64-reg cap -> occ 4
// so all 512 CTAs run in a single wave.
// ==============================================================================
__global__ __launch_bounds__(256, 4) void laplace_kern()
{
    __shared__ uint32_t qs[32][64];   // [d2][i] half2
    __shared__ uint32_t ks[32][64];   // [d2][j] half2

    const int tid = threadIdx.x;
    const int tx  = tid & 15;
    const int ty  = tid >> 4;
    const int it  = blockIdx.x;
    const int bh  = blockIdx.y;

    const float* Q  = &g_qkv[0][bh][it*64][0];
    const float* Kp = &g_qkv[1][bh][0][0];

#pragma unroll
    for (int r = 0; r < 4; r++) {
        int idx = r*1024 + tid*4;
        int i = idx >> 6, d = idx & 63;
        float4 v = *(const float4*)(Q + i*64 + d);
        qs[(d>>1)    ][i] = h2u(__floats2half2_rn(v.x, v.y));
        qs[(d>>1) + 1][i] = h2u(__floats2half2_rn(v.z, v.w));
    }

    float rs[4] = {0.f, 0.f, 0.f, 0.f};
    char* kout = (char*)&g_kern_h[bh][it*64][0];

    for (int jt = 0; jt < 16; jt++) {
#pragma unroll
        for (int r = 0; r < 4; r++) {
            int idx = r*1024 + tid*4;
            int j = idx >> 6, d = idx & 63;
            float4 v = *(const float4*)(Kp + (jt*64 + j)*64 + d);
            ks[(d>>1)    ][j] = h2u(__floats2half2_rn(v.x, v.y));
            ks[(d>>1) + 1][j] = h2u(__floats2half2_rn(v.z, v.w));
        }
        __syncthreads();

        __half2 acc[4][4];
#pragma unroll
        for (int ii = 0; ii < 4; ii++)
#pragma unroll
            for (int jj = 0; jj < 4; jj++)
                acc[ii][jj] = __half2half2(__ushort_as_half(0));

#pragma unroll
        for (int d2 = 0; d2 < 32; d2++) {
            uint4 qv = *(const uint4*)&qs[d2][ty*4];
            uint4 kv = *(const uint4*)&ks[d2][tx*4];
            uint32_t q2[4] = {qv.x, qv.y, qv.z, qv.w};
            uint32_t k2[4] = {kv.x, kv.y, kv.z, kv.w};
#pragma unroll
            for (int ii = 0; ii < 4; ii++)
#pragma unroll
                for (int jj = 0; jj < 4; jj++)
                    acc[ii][jj] = __hadd2(acc[ii][jj],
                                   __habs2(__hsub2(u2h(q2[ii]), u2h(k2[jj]))));
        }

#pragma unroll
        for (int ii = 0; ii < 4; ii++) {
            float op[4];
#pragma unroll
            for (int jj = 0; jj < 4; jj++) {
                float2 fa = __half22float2(acc[ii][jj]);
                float dist = fa.x + fa.y;
                float kv = __expf(-0.0625f * dist);
                op[jj] = kv;
                rs[ii] += kv;
            }
            __half2 p01 = __floats2half2_rn(op[0], op[1]);
            __half2 p23 = __floats2half2_rn(op[2], op[3]);
            *(uint2*)(kout + ((size_t)(ty*4 + ii)*1024 + jt*64 + tx*4)*2)
                = make_uint2(h2u(p01), h2u(p23));
        }
        __syncthreads();
    }

#pragma unroll
    for (int ii = 0; ii < 4; ii++) {
        float v = rs[ii];
        v += __shfl_xor_sync(0xffffffffu, v, 1);
        v += __shfl_xor_sync(0xffffffffu, v, 2);
        v += __shfl_xor_sync(0xffffffffu, v, 4);
        v += __shfl_xor_sync(0xffffffffu, v, 8);
        if (tx == 0) g_rowsum[bh][it*64 + ty*4 + ii] = v;
    }
}

// ==============================================================================
// attnv_tc: (kern_fp16 @ v) via m16n8k16 HMMA; v fp16 hi/lo (2 mmas).
// M-tile 64 -> grid 512, occ 4 (more outstanding loads; latency-limited before).
// + row normalize + depthwise conv; y emitted as fp16 (g_yh).
// smem/stage: A 64x144B (9216) | vh 9216 | vl 9216 = 27648; x2 stages.
// ==============================================================================
#define AV_STAGE 27648
#define AV_SMEM  (2*AV_STAGE)

__global__ __launch_bounds__(256, 4) void attnv_tc(const float* __restrict__ dwc_w,
                                                   const float* __restrict__ dwc_b)
{
    extern __shared__ char sm[];
    const int tid  = threadIdx.x;
    const int warp = tid >> 5;
    const int lane = tid & 31;
    const int gr   = lane >> 2;
    const int tg   = lane & 3;
    const int wm   = (warp & 3) * 16;     // 4 warps in M (64 rows)
    const int wn   = (warp >> 2) * 32;    // 2 warps in N (64 cols)
    const int it   = blockIdx.x;          // 0..15 (64-row tiles)
    const int bh   = blockIdx.y;
    const int bb   = bh >> 4;
    const int h    = bh & 15;

    const __half* Kh = &g_kern_h[bh][0][0];
    const float*  V  = &g_qkv[2][bh][0][0];
    const uint32_t smBase = smem_u32(sm);

    float acc[4][4];
#pragma unroll
    for (int n = 0; n < 4; n++)
#pragma unroll
        for (int e = 0; e < 4; e++) acc[n][e] = 0.f;

    const int arow = tid >> 2, ach = (tid & 3) * 2;   // kern cp.async: 2 chunks
    const int vrow = tid >> 4, vd = (tid & 15) * 4;   // v ldg/sts

    auto issue_kern = [&](int st, int k0) {
        const uint32_t dst = smBase + st * AV_STAGE + arow * 144;
        const __half* src = Kh + (size_t)(it * 64 + arow) * 1024 + k0;
        cp16(dst + ach * 16,       src + ach * 8);
        cp16(dst + (ach + 1) * 16, src + (ach + 1) * 8);
        asm volatile("cp.async.commit_group;\n");
    };
    auto ldg_v = [&](int k0, float4* vr) {
#pragma unroll
        for (int q = 0; q < 4; q++)
            vr[q] = *(const float4*)(V + (size_t)(k0 + vrow + 16 * q) * 64 + vd);
    };
    auto sts_v = [&](int st, const float4* vr) {
        char* vhB = sm + st * AV_STAGE + 9216;
        char* vlB = sm + st * AV_STAGE + 18432;
#pragma unroll
        for (int q = 0; q < 4; q++) {
            int r = vrow + 16 * q;
            float4 vv = vr[q];
            __half hx = __float2half_rn(vv.x), hy = __float2half_rn(vv.y);
            __half hz = __float2half_rn(vv.z), hw = __float2half_rn(vv.w);
            __half2 hi0 = __halves2half2(hx, hy), hi1 = __halves2half2(hz, hw);
            __half2 lo0 = __floats2half2_rn(vv.x - __half2float(hx),
                                            vv.y - __half2float(hy));
            __half2 lo1 = __floats2half2_rn(vv.z - __half2float(hz),
                                            vv.w - __half2float(hw));
            *(uint2*)(vhB + r * 144 + vd * 2) = make_uint2(h2u(hi0), h2u(hi1));
            *(uint2*)(vlB + r * 144 + vd * 2) = make_uint2(h2u(lo0), h2u(lo1));
        }
    };

    const uint32_t aOff = (uint32_t)((wm + (lane & 7) + ((lane >> 3) & 1) * 8) * 144
                                     + (lane >> 4) * 16);
    const uint32_t bRow = (uint32_t)((lane & 15) * 144 + wn * 2);

    issue_kern(0, 0);
    {
        float4 vr[4];
        ldg_v(0, vr);
        sts_v(0, vr);
    }

    for (int kt = 0; kt < 16; kt++) {
        const int cur = kt & 1;
        asm volatile("cp.async.wait_group 0;\n");
        __syncthreads();

        float4 vr[4];
        if (kt < 15) {
            issue_kern(cur ^ 1, (kt + 1) * 64);
            ldg_v((kt + 1) * 64, vr);
        }

        const uint32_t aB  = smBase + cur * AV_STAGE + aOff;
        const uint32_t vhB = smBase + cur * AV_STAGE + 9216  + bRow;
        const uint32_t vlB = smBase + cur * AV_STAGE + 18432 + bRow;
#pragma unroll
        for (int k16 = 0; k16 < 4; k16++) {
            uint32_t a0, a1, a2, a3;
            ldsm4(a0, a1, a2, a3, aB + k16 * 32);
#pragma unroll
            for (int nf = 0; nf < 4; nf++) {
                uint32_t bh0, bh1, bl0, bl1;
                ldsm2t(bh0, bh1, vhB + k16 * 2304 + nf * 16);
                ldsm2t(bl0, bl1, vlB + k16 * 2304 + nf * 16);
                mma_f16(acc[nf], a0, a1, a2, a3, bh0, bh1);
                mma_f16(acc[nf], a0, a1, a2, a3, bl0, bl1);
            }
        }

        if (kt < 15) sts_v(cur ^ 1, vr);
    }

    // ---- epilogue: normalize + depthwise conv; emit y as fp16 ----
    const int m0 = it * 64 + wm + gr;
#pragma unroll
    for (int nf = 0; nf < 4; nf++) {
        const int dl = wn + nf * 8 + tg * 2;
        const int c  = h * 64 + dl;
        const float w0a = dwc_w[c*3+0], w1a = dwc_w[c*3+1], w2a = dwc_w[c*3+2];
        const float b0a = dwc_b[c];
        const float w0b = dwc_w[c*3+3], w1b = dwc_w[c*3+4], w2b = dwc_w[c*3+5];
        const float b1b = dwc_b[c+1];
#pragma unroll
        for (int half = 0; half < 2; half++) {
            const int s = m0 + half * 8;
            const float sc = 1.0f / (g_rowsum[bh][s] + 1e-6f);
            float o0 = acc[nf][half*2 + 0] * sc;
            float o1 = acc[nf][half*2 + 1] * sc;
            float2 v0 = *(const float2*)&V[(size_t)s*64 + dl];
            float2 vm = (s > 0)       ? *(const float2*)&V[(size_t)(s-1)*64 + dl]
                                      : make_float2(0.f, 0.f);
            float2 vp = (s < SEQ - 1) ? *(const float2*)&V[(size_t)(s+1)*64 + dl]
                                      : make_float2(0.f, 0.f);
            o0 += w0a*vm.x + w1a*v0.x + w2a*vp.x + b0a;
            o1 += w0b*vm.y + w1b*v0.y + w2b*vp.y + b1b;
            const size_t oidx = (size_t)(bb*SEQ + s) * 1024 + c;
            *(uint32_t*)&g_yh[oidx] = h2u(__floats2half2_rn(o0, o1));
        }
    }
}

// ==============================================================================
extern "C" void kernel_launch(void* const* d_in, const int* in_sizes, int n_in,
                              void* d_out, int out_size)
{
    const float* x      = (const float*)d_in[0];
    const float* qkv_w  = (const float*)d_in[1];
    const float* qkv_b  = (const float*)d_in[2];
    const float* proj_w = (const float*)d_in[3];
    const float* proj_b = (const float*)d_in[4];
    const float* dwc_w  = (const float*)d_in[5];
    const float* dwc_b  = (const float*)d_in[6];
    float* out = (float*)d_out;

    cudaFuncSetAttribute(hgemm_nt<1>, cudaFuncAttributeMaxDynamicSharedMemorySize, HG_SMEM);
    cudaFuncSetAttribute(hgemm_nt<0>, cudaFuncAttributeMaxDynamicSharedMemorySize, HG_SMEM);
    cudaFuncSetAttribute(attnv_tc,    cudaFuncAttributeMaxDynamicSharedMemorySize, AV_SMEM);

    // 0) convert x / weights to fp16 scratch
    prep_f16<<<dim3(3072, 3), 256>>>(x, qkv_w, proj_w);
    // 1) qkv projection (plain fp16 HMMA), scatter to q/k/v (fp32)
    hgemm_nt<1><<<dim3(24, 16), 256, HG_SMEM>>>(qkv_b, nullptr, 3072, 1024);
    // 2) Laplacian L1 kernel matrix (fp16 half2 math, occ 4) + fp32 row sums
    laplace_kern<<<dim3(16, 32), 256>>>();
    // 3) kern_fp16 @ v (fp16 HMMA, M64 tiles, occ 4) + normalize + dwc -> y
    attnv_tc<<<dim3(16, 32), 256, AV_SMEM>>>(dwc_w, dwc_b);
    // 4) output projection (plain fp16 HMMA) -> d_out
    hgemm_nt<0><<<dim3(8, 16), 256, HG_SMEM>>>(proj_b, out, 1024, 1024);
}

// round 10
// speedup vs baseline: 1.8487x; 1.1009x over previous
#include <cuda_runtime.h>
#include <cuda_fp16.h>
#include <cstdint>

#define SEQ 1024
#define DIMC 1024
#define NHEADS 16
#define HDIM 64
#define NBATCH 2
#define NBH (NBATCH*NHEADS)   // 32

// ---------------- scratch (device globals; no runtime allocation) -------------
__device__ float  g_v[NBH][SEQ][HDIM];         // 8 MB   v (fp32, attnv+dwc)
__device__ __half g_qk_h[2][NBH][SEQ][HDIM];   // 8 MB   q,k fp16 (laplace only)
__device__ __half g_kern_h[NBH][SEQ][SEQ];     // 67 MB  fp16 kernel matrix
__device__ float  g_rowsum[NBH][SEQ];          // row sums (fp32)
__device__ __half g_xh[2048*1024];             // fp16 x
__device__ __half g_wqh[3072*1024];            // fp16 qkv_w
__device__ __half g_wph[1024*1024];            // fp16 proj_w
__device__ __half g_yh[2048*1024];             // fp16 pre-projection activations

// ---------------- helpers ------------------------------------------------------
__device__ __forceinline__ uint32_t smem_u32(const void* p) {
    return (uint32_t)__cvta_generic_to_shared(p);
}
__device__ __forceinline__ void cp16(uint32_t s, const void* g) {
    asm volatile("cp.async.cg.shared.global [%0], [%1], 16;\n" :: "r"(s), "l"(g));
}
__device__ __forceinline__ void mma_f16(float c[4],
        uint32_t a0, uint32_t a1, uint32_t a2, uint32_t a3,
        uint32_t b0, uint32_t b1) {
    asm volatile(
        "mma.sync.aligned.m16n8k16.row.col.f32.f16.f16.f32 "
        "{%0,%1,%2,%3}, {%4,%5,%6,%7}, {%8,%9}, {%0,%1,%2,%3};"
        : "+f"(c[0]), "+f"(c[1]), "+f"(c[2]), "+f"(c[3])
        : "r"(a0), "r"(a1), "r"(a2), "r"(a3), "r"(b0), "r"(b1));
}
__device__ __forceinline__ void ldsm4(uint32_t& r0, uint32_t& r1,
                                      uint32_t& r2, uint32_t& r3, uint32_t a) {
    asm volatile("ldmatrix.sync.aligned.m8n8.x4.shared.b16 {%0,%1,%2,%3}, [%4];"
                 : "=r"(r0), "=r"(r1), "=r"(r2), "=r"(r3) : "r"(a));
}
__device__ __forceinline__ void ldsm2t(uint32_t& r0, uint32_t& r1, uint32_t a) {
    asm volatile("ldmatrix.sync.aligned.m8n8.x2.trans.shared.b16 {%0,%1}, [%2];"
                 : "=r"(r0), "=r"(r1) : "r"(a));
}
__device__ __forceinline__ uint32_t h2u(__half2 h) { return *(uint32_t*)&h; }
__device__ __forceinline__ __half2 u2h(uint32_t u) { return *(__half2*)&u; }

// ==============================================================================
// Prepass: convert x / qkv_w / proj_w to fp16 scratch copies.
// ==============================================================================
__global__ __launch_bounds__(256) void prep_f16(const float* __restrict__ x,
                                                const float* __restrict__ wq,
                                                const float* __restrict__ wp)
{
    const float4* src; __half* dh; int n4;
    if (blockIdx.y == 0)      { src = (const float4*)x;  dh = g_xh;  n4 = 524288; }
    else if (blockIdx.y == 1) { src = (const float4*)wq; dh = g_wqh; n4 = 786432; }
    else                      { src = (const float4*)wp; dh = g_wph; n4 = 262144; }
    int i = blockIdx.x * 256 + threadIdx.x;
    if (i < n4) {
        float4 v = src[i];
        ((uint2*)dh)[i] = make_uint2(h2u(__floats2half2_rn(v.x, v.y)),
                                     h2u(__floats2half2_rn(v.z, v.w)));
    }
}

// ==============================================================================
// Plain fp16 tensor-core GEMM (NT): C = A @ B^T + bias, fp32 accumulate.
// MODE 1: A=x, B=qkv_w; scatter q,k as fp16 (g_qk_h), v as fp32 (g_v).
// MODE 0: A=y, B=proj_w, row-major fp32 C.
// ==============================================================================
#define HG_STAGE 20480
#define HG_SMEM  (2*HG_STAGE)

template<int MODE>
__global__ __launch_bounds__(256, 2) void hgemm_nt(
    const float* __restrict__ bias, float* __restrict__ C, int N, int K)
{
    extern __shared__ char smh[];
    const uint32_t smB = smem_u32(smh);

    const int tid  = threadIdx.x;
    const int warp = tid >> 5;
    const int lane = tid & 31;
    const int gr   = lane >> 2;
    const int tg   = lane & 3;
    const int wm   = (warp & 3) * 32;
    const int wn   = (warp >> 2) * 64;
    const int mb   = blockIdx.y * 128;
    const int nb   = blockIdx.x * 128;

    const __half* AH = (MODE == 1) ? g_xh  : g_yh;
    const __half* BH = (MODE == 1) ? g_wqh : g_wph;

    const int row = tid >> 1;
    const int cp  = (tid & 1) * 2;
    const __half* aHg = AH + (size_t)(mb + row) * K + cp * 8;
    const __half* bHg = BH + (size_t)(nb + row) * K + cp * 8;
    const uint32_t stDst = row * 80 + cp * 16;

    auto load_st = [&](int st, int k0) {
        const uint32_t d = smB + st * HG_STAGE + stDst;
        cp16(d,         aHg + k0); cp16(d + 16,         aHg + k0 + 8);
        cp16(d + 10240, bHg + k0); cp16(d + 10240 + 16, bHg + k0 + 8);
        asm volatile("cp.async.commit_group;\n");
    };

    float acc[2][8][4];
#pragma unroll
    for (int i = 0; i < 2; i++)
#pragma unroll
        for (int j = 0; j < 8; j++)
#pragma unroll
            for (int r = 0; r < 4; r++) acc[i][j][r] = 0.f;

    const uint32_t aOff = (wm + (lane & 15)) * 80 + (lane >> 4) * 16;
    const uint32_t bOff = (wn + (lane & 15)) * 80 + (lane >> 4) * 16 + 10240;

    const int nK = K / 32;
    load_st(0, 0);

    for (int kt = 0; kt < nK; kt++) {
        asm volatile("cp.async.wait_group 0;\n");
        __syncthreads();
        if (kt + 1 < nK) load_st((kt + 1) & 1, (kt + 1) * 32);
        const uint32_t sb = smB + (kt & 1) * HG_STAGE;

#pragma unroll
        for (int s = 0; s < 2; s++) {
            uint32_t ah[2][4];
#pragma unroll
            for (int i = 0; i < 2; i++)
                ldsm4(ah[i][0], ah[i][1], ah[i][2], ah[i][3],
                      sb + aOff + i * 1280 + s * 32);
#pragma unroll
            for (int j = 0; j < 4; j++) {
                uint32_t bh_[4];
                ldsm4(bh_[0], bh_[1], bh_[2], bh_[3],
                      sb + bOff + j * 1280 + s * 32);
#pragma unroll
                for (int i = 0; i < 2; i++) {
                    mma_f16(acc[i][2*j  ], ah[i][0], ah[i][1], ah[i][2], ah[i][3], bh_[0], bh_[2]);
                    mma_f16(acc[i][2*j+1], ah[i][0], ah[i][1], ah[i][2], ah[i][3], bh_[1], bh_[3]);
                }
            }
        }
    }

#pragma unroll
    for (int i = 0; i < 2; i++) {
#pragma unroll
        for (int j = 0; j < 8; j++) {
            const int r0 = mb + wm + i * 16 + gr;
            const int c0 = nb + wn + j * 8 + 2 * tg;
            const float bia0 = bias[c0], bia1 = bias[c0 + 1];
            if (MODE == 1) {
#pragma unroll
                for (int e = 0; e < 4; e++) {
                    const int m = r0 + (e >> 1) * 8;
                    const int n = c0 + (e & 1);
                    const float v = acc[i][j][e] + ((e & 1) ? bia1 : bia0);
                    const int tsel = n >> 10, rem = n & 1023;
                    const int h = rem >> 6, d = rem & 63;
                    const int bb = m >> 10, s = m & 1023;
                    if (tsel < 2)
                        g_qk_h[tsel][bb * NHEADS + h][s][d] = __float2half_rn(v);
                    else
                        g_v[bb * NHEADS + h][s][d] = v;
                }
            } else {
                float2 lo = make_float2(acc[i][j][0] + bia0, acc[i][j][1] + bia1);
                float2 hi = make_float2(acc[i][j][2] + bia0, acc[i][j][3] + bia1);
                *(float2*)&C[(size_t)r0 * N + c0]       = lo;
                *(float2*)&C[(size_t)(r0 + 8) * N + c0] = hi;
            }
        }
    }
}

// ==============================================================================
// Laplacian kernel: fp16 inputs, half2 distance math, double-buffered k tiles
// (register prefetch, one barrier per jt), 68-word padded smem rows.
// ==============================================================================
__global__ __launch_bounds__(256, 4) void laplace_kern()
{
    __shared__ uint32_t qs[32][68];       // [d2][i] half2, padded
    __shared__ uint32_t ks[2][32][68];    // [buf][d2][j] half2, padded

    const int tid = threadIdx.x;
    const int tx  = tid & 15;
    const int ty  = tid >> 4;
    const int it  = blockIdx.x;
    const int bh  = blockIdx.y;

    const __half* Q  = &g_qk_h[0][bh][it*64][0];
    const __half* Kp = &g_qk_h[1][bh][0][0];

    // q tile once (fp16 direct)
#pragma unroll
    for (int r = 0; r < 2; r++) {
        int idxh = r*2048 + tid*8;
        int i = idxh >> 6, d = idxh & 63;
        uint4 v = *(const uint4*)(Q + i*64 + d);
        int d2 = d >> 1;
        qs[d2+0][i] = v.x; qs[d2+1][i] = v.y;
        qs[d2+2][i] = v.z; qs[d2+3][i] = v.w;
    }

    uint4 kr[2];
    auto ldg_k = [&](int jt) {
#pragma unroll
        for (int r = 0; r < 2; r++) {
            int idxh = r*2048 + tid*8;
            int j = idxh >> 6, d = idxh & 63;
            kr[r] = *(const uint4*)(Kp + (size_t)(jt*64 + j)*64 + d);
        }
    };
    auto sts_k = [&](int buf) {
#pragma unroll
        for (int r = 0; r < 2; r++) {
            int idxh = r*2048 + tid*8;
            int j = idxh >> 6, d = idxh & 63;
            int d2 = d >> 1;
            ks[buf][d2+0][j] = kr[r].x; ks[buf][d2+1][j] = kr[r].y;
            ks[buf][d2+2][j] = kr[r].z; ks[buf][d2+3][j] = kr[r].w;
        }
    };

    ldg_k(0); sts_k(0); ldg_k(1);
    __syncthreads();

    float rs[4] = {0.f, 0.f, 0.f, 0.f};
    char* kout = (char*)&g_kern_h[bh][it*64][0];

    for (int jt = 0; jt < 16; jt++) {
        if (jt < 15) sts_k((jt + 1) & 1);   // stage next (regs already loaded)
        if (jt < 14) ldg_k(jt + 2);         // prefetch next+1 (latency hidden)

        __half2 acc[4][4];
#pragma unroll
        for (int ii = 0; ii < 4; ii++)
#pragma unroll
            for (int jj = 0; jj < 4; jj++)
                acc[ii][jj] = __half2half2(__ushort_as_half(0));

        const int buf = jt & 1;
#pragma unroll
        for (int d2 = 0; d2 < 32; d2++) {
            uint4 qv = *(const uint4*)&qs[d2][ty*4];
            uint4 kv = *(const uint4*)&ks[buf][d2][tx*4];
            uint32_t q2[4] = {qv.x, qv.y, qv.z, qv.w};
            uint32_t k2[4] = {kv.x, kv.y, kv.z, kv.w};
#pragma unroll
            for (int ii = 0; ii < 4; ii++)
#pragma unroll
                for (int jj = 0; jj < 4; jj++)
                    acc[ii][jj] = __hadd2(acc[ii][jj],
                                   __habs2(__hsub2(u2h(q2[ii]), u2h(k2[jj]))));
        }

#pragma unroll
        for (int ii = 0; ii < 4; ii++) {
            float op[4];
#pragma unroll
            for (int jj = 0; jj < 4; jj++) {
                float2 fa = __half22float2(acc[ii][jj]);
                float dist = fa.x + fa.y;
                float kv = __expf(-0.0625f * dist);
                op[jj] = kv;
                rs[ii] += kv;
            }
            __half2 p01 = __floats2half2_rn(op[0], op[1]);
            __half2 p23 = __floats2half2_rn(op[2], op[3]);
            *(uint2*)(kout + ((size_t)(ty*4 + ii)*1024 + jt*64 + tx*4)*2)
                = make_uint2(h2u(p01), h2u(p23));
        }
        __syncthreads();
    }

#pragma unroll
    for (int ii = 0; ii < 4; ii++) {
        float v = rs[ii];
        v += __shfl_xor_sync(0xffffffffu, v, 1);
        v += __shfl_xor_sync(0xffffffffu, v, 2);
        v += __shfl_xor_sync(0xffffffffu, v, 4);
        v += __shfl_xor_sync(0xffffffffu, v, 8);
        if (tx == 0) g_rowsum[bh][it*64 + ty*4 + ii] = v;
    }
}

// ==============================================================================
// attnv_tc (round-8 proven M128 version): (kern_fp16 @ v), v fp16 hi/lo (2 mmas)
// + row normalize + depthwise conv; y emitted as fp16 (g_yh).
// ==============================================================================
#define AV_STAGE 36864
#define AV_SMEM  (2*AV_STAGE)

__global__ __launch_bounds__(256, 2) void attnv_tc(const float* __restrict__ dwc_w,
                                                   const float* __restrict__ dwc_b)
{
    extern __shared__ char sm[];
    const int tid  = threadIdx.x;
    const int warp = tid >> 5;
    const int lane = tid & 31;
    const int gr   = lane >> 2;
    const int tg   = lane & 3;
    const int it   = blockIdx.x;
    const int bh   = blockIdx.y;
    const int bb   = bh >> 4;
    const int h    = bh & 15;

    const __half* Kh = &g_kern_h[bh][0][0];
    const float*  V  = &g_v[bh][0][0];
    const uint32_t smBase = smem_u32(sm);

    float acc[8][4];
#pragma unroll
    for (int n = 0; n < 8; n++)
#pragma unroll
        for (int e = 0; e < 4; e++) acc[n][e] = 0.f;

    const int arow = tid >> 3, achk = tid & 7;
    const int vrow = tid >> 4, vd = (tid & 15) * 4;

    auto issue_kern = [&](int st, int k0) {
        const uint32_t dst = smBase + st * AV_STAGE;
#pragma unroll
        for (int q = 0; q < 4; q++) {
            int r = arow + 32 * q;
            cp16(dst + r * 144 + achk * 16,
                 Kh + (size_t)(it * 128 + r) * 1024 + k0 + achk * 8);
        }
        asm volatile("cp.async.commit_group;\n");
    };
    auto ldg_v = [&](int k0, float4* vr) {
#pragma unroll
        for (int q = 0; q < 4; q++)
            vr[q] = *(const float4*)(V + (size_t)(k0 + vrow + 16 * q) * 64 + vd);
    };
    auto sts_v = [&](int st, const float4* vr) {
        char* vhB = sm + st * AV_STAGE + 18432;
        char* vlB = sm + st * AV_STAGE + 27648;
#pragma unroll
        for (int q = 0; q < 4; q++) {
            int r = vrow + 16 * q;
            float4 vv = vr[q];
            __half hx = __float2half_rn(vv.x), hy = __float2half_rn(vv.y);
            __half hz = __float2half_rn(vv.z), hw = __float2half_rn(vv.w);
            __half2 hi0 = __halves2half2(hx, hy), hi1 = __halves2half2(hz, hw);
            __half2 lo0 = __floats2half2_rn(vv.x - __half2float(hx),
                                            vv.y - __half2float(hy));
            __half2 lo1 = __floats2half2_rn(vv.z - __half2float(hz),
                                            vv.w - __half2float(hw));
            *(uint2*)(vhB + r * 144 + vd * 2) = make_uint2(h2u(hi0), h2u(hi1));
            *(uint2*)(vlB + r * 144 + vd * 2) = make_uint2(h2u(lo0), h2u(lo1));
        }
    };

    const uint32_t aOff = (uint32_t)((warp * 16 + (lane & 7) + ((lane >> 3) & 1) * 8) * 144
                                     + (lane >> 4) * 16);
    const uint32_t bRow = (uint32_t)((lane & 15) * 144);

    issue_kern(0, 0);
    {
        float4 vr[4];
        ldg_v(0, vr);
        sts_v(0, vr);
    }

    for (int kt = 0; kt < 16; kt++) {
        const int cur = kt & 1;
        asm volatile("cp.async.wait_group 0;\n");
        __syncthreads();

        float4 vr[4];
        if (kt < 15) {
            issue_kern(cur ^ 1, (kt + 1) * 64);
            ldg_v((kt + 1) * 64, vr);
        }

        const uint32_t aB  = smBase + cur * AV_STAGE + aOff;
        const uint32_t vhB = smBase + cur * AV_STAGE + 18432 + bRow;
        const uint32_t vlB = smBase + cur * AV_STAGE + 27648 + bRow;
#pragma unroll
        for (int k16 = 0; k16 < 4; k16++) {
            uint32_t a0, a1, a2, a3;
            ldsm4(a0, a1, a2, a3, aB + k16 * 32);
#pragma unroll
            for (int nf = 0; nf < 8; nf++) {
                uint32_t bh0, bh1, bl0, bl1;
                ldsm2t(bh0, bh1, vhB + k16 * 2304 + nf * 16);
                ldsm2t(bl0, bl1, vlB + k16 * 2304 + nf * 16);
                mma_f16(acc[nf], a0, a1, a2, a3, bh0, bh1);
                mma_f16(acc[nf], a0, a1, a2, a3, bl0, bl1);
            }
        }

        if (kt < 15) sts_v(cur ^ 1, vr);
    }

    const int m0 = it * 128 + warp * 16 + gr;
#pragma unroll
    for (int nf = 0; nf < 8; nf++) {
        const int dl = nf * 8 + tg * 2;
        const int c  = h * 64 + dl;
        const float w0a = dwc_w[c*3+0], w1a = dwc_w[c*3+1], w2a = dwc_w[c*3+2];
        const float b0a = dwc_b[c];
        const float w0b = dwc_w[c*3+3], w1b = dwc_w[c*3+4], w2b = dwc_w[c*3+5];
        const float b1b = dwc_b[c+1];
#pragma unroll
        for (int half = 0; half < 2; half++) {
            const int s = m0 + half * 8;
            const float sc = 1.0f / (g_rowsum[bh][s] + 1e-6f);
            float o0 = acc[nf][half*2 + 0] * sc;
            float o1 = acc[nf][half*2 + 1] * sc;
            float2 v0 = *(const float2*)&V[(size_t)s*64 + dl];
            float2 vm = (s > 0)       ? *(const float2*)&V[(size_t)(s-1)*64 + dl]
                                      : make_float2(0.f, 0.f);
            float2 vp = (s < SEQ - 1) ? *(const float2*)&V[(size_t)(s+1)*64 + dl]
                                      : make_float2(0.f, 0.f);
            o0 += w0a*vm.x + w1a*v0.x + w2a*vp.x + b0a;
            o1 += w0b*vm.y + w1b*v0.y + w2b*vp.y + b1b;
            const size_t oidx = (size_t)(bb*SEQ + s) * 1024 + c;
            *(uint32_t*)&g_yh[oidx] = h2u(__floats2half2_rn(o0, o1));
        }
    }
}

// ==============================================================================
extern "C" void kernel_launch(void* const* d_in, const int* in_sizes, int n_in,
                              void* d_out, int out_size)
{
    const float* x      = (const float*)d_in[0];
    const float* qkv_w  = (const float*)d_in[1];
    const float* qkv_b  = (const float*)d_in[2];
    const float* proj_w = (const float*)d_in[3];
    const float* proj_b = (const float*)d_in[4];
    const float* dwc_w  = (const float*)d_in[5];
    const float* dwc_b  = (const float*)d_in[6];
    float* out = (float*)d_out;

    cudaFuncSetAttribute(hgemm_nt<1>, cudaFuncAttributeMaxDynamicSharedMemorySize, HG_SMEM);
    cudaFuncSetAttribute(hgemm_nt<0>, cudaFuncAttributeMaxDynamicSharedMemorySize, HG_SMEM);
    cudaFuncSetAttribute(attnv_tc,    cudaFuncAttributeMaxDynamicSharedMemorySize, AV_SMEM);

    // 0) convert x / weights to fp16 scratch
    prep_f16<<<dim3(3072, 3), 256>>>(x, qkv_w, proj_w);
    // 1) qkv projection (fp16 HMMA); q,k -> fp16, v -> fp32
    hgemm_nt<1><<<dim3(24, 16), 256, HG_SMEM>>>(qkv_b, nullptr, 3072, 1024);
    // 2) Laplacian L1 kernel matrix (double-buffered, fp16 in/out) + row sums
    laplace_kern<<<dim3(16, 32), 256>>>();
    // 3) kern_fp16 @ v (fp16 HMMA, M128 tiles) + normalize + dwc -> y (fp16)
    attnv_tc<<<dim3(8, 32), 256, AV_SMEM>>>(dwc_w, dwc_b);
    // 4) output projection (fp16 HMMA) -> d_out
    hgemm_nt<0><<<dim3(8, 16), 256, HG_SMEM>>>(proj_b, out, 1024, 1024);
}

// round 11
// speedup vs baseline: 2.0665x; 1.1178x over previous
#include <cuda_runtime.h>
#include <cuda_fp16.h>
#include <cstdint>

#define SEQ 1024
#define DIMC 1024
#define NHEADS 16
#define HDIM 64
#define NBATCH 2
#define NBH (NBATCH*NHEADS)   // 32

// ---------------- scratch (device globals; no runtime allocation) -------------
__device__ float    g_v[NBH][SEQ][HDIM];        // 8 MB  v fp32 (dwc epilogue)
__device__ __half   g_vh[NBH][SEQ][HDIM];       // 4 MB  v fp16 (mma operand)
__device__ uint32_t g_qkT[2][NBH][32][1024];    // 8 MB  q,k transposed: [d2][s] half2
__device__ __half   g_xh[2048*1024];            // fp16 x
__device__ __half   g_wqh[3072*1024];           // fp16 qkv_w
__device__ __half   g_wph[1024*1024];           // fp16 proj_w
__device__ __half   g_yh[2048*1024];            // fp16 pre-projection activations

// ---------------- helpers ------------------------------------------------------
__device__ __forceinline__ uint32_t smem_u32(const void* p) {
    return (uint32_t)__cvta_generic_to_shared(p);
}
__device__ __forceinline__ void cp16(uint32_t s, const void* g) {
    asm volatile("cp.async.cg.shared.global [%0], [%1], 16;\n" :: "r"(s), "l"(g));
}
__device__ __forceinline__ void mma_f16(float c[4],
        uint32_t a0, uint32_t a1, uint32_t a2, uint32_t a3,
        uint32_t b0, uint32_t b1) {
    asm volatile(
        "mma.sync.aligned.m16n8k16.row.col.f32.f16.f16.f32 "
        "{%0,%1,%2,%3}, {%4,%5,%6,%7}, {%8,%9}, {%0,%1,%2,%3};"
        : "+f"(c[0]), "+f"(c[1]), "+f"(c[2]), "+f"(c[3])
        : "r"(a0), "r"(a1), "r"(a2), "r"(a3), "r"(b0), "r"(b1));
}
__device__ __forceinline__ void ldsm4(uint32_t& r0, uint32_t& r1,
                                      uint32_t& r2, uint32_t& r3, uint32_t a) {
    asm volatile("ldmatrix.sync.aligned.m8n8.x4.shared.b16 {%0,%1,%2,%3}, [%4];"
                 : "=r"(r0), "=r"(r1), "=r"(r2), "=r"(r3) : "r"(a));
}
__device__ __forceinline__ void ldsm4t(uint32_t& r0, uint32_t& r1,
                                       uint32_t& r2, uint32_t& r3, uint32_t a) {
    asm volatile("ldmatrix.sync.aligned.m8n8.x4.trans.shared.b16 {%0,%1,%2,%3}, [%4];"
                 : "=r"(r0), "=r"(r1), "=r"(r2), "=r"(r3) : "r"(a));
}
__device__ __forceinline__ uint32_t h2u(__half2 h) { return *(uint32_t*)&h; }
__device__ __forceinline__ __half2 u2h(uint32_t u) { return *(__half2*)&u; }

// ==============================================================================
// Prepass: convert x / qkv_w / proj_w to fp16 scratch copies.
// ==============================================================================
__global__ __launch_bounds__(256) void prep_f16(const float* __restrict__ x,
                                                const float* __restrict__ wq,
                                                const float* __restrict__ wp)
{
    const float4* src; __half* dh; int n4;
    if (blockIdx.y == 0)      { src = (const float4*)x;  dh = g_xh;  n4 = 524288; }
    else if (blockIdx.y == 1) { src = (const float4*)wq; dh = g_wqh; n4 = 786432; }
    else                      { src = (const float4*)wp; dh = g_wph; n4 = 262144; }
    int i = blockIdx.x * 256 + threadIdx.x;
    if (i < n4) {
        float4 v = src[i];
        ((uint2*)dh)[i] = make_uint2(h2u(__floats2half2_rn(v.x, v.y)),
                                     h2u(__floats2half2_rn(v.z, v.w)));
    }
}

// ==============================================================================
// Plain fp16 tensor-core GEMM (NT): C = A @ B^T + bias, fp32 accumulate.
// MODE 1: A=x, B=qkv_w; q,k -> g_qkT (transposed half2), v -> g_v + g_vh.
// MODE 0: A=y, B=proj_w, row-major fp32 C.
// ==============================================================================
#define HG_STAGE 20480
#define HG_SMEM  (2*HG_STAGE)

template<int MODE>
__global__ __launch_bounds__(256, 2) void hgemm_nt(
    const float* __restrict__ bias, float* __restrict__ C, int N, int K)
{
    extern __shared__ char smh[];
    const uint32_t smB = smem_u32(smh);

    const int tid  = threadIdx.x;
    const int warp = tid >> 5;
    const int lane = tid & 31;
    const int gr   = lane >> 2;
    const int tg   = lane & 3;
    const int wm   = (warp & 3) * 32;
    const int wn   = (warp >> 2) * 64;
    const int mb   = blockIdx.y * 128;
    const int nb   = blockIdx.x * 128;

    const __half* AH = (MODE == 1) ? g_xh  : g_yh;
    const __half* BH = (MODE == 1) ? g_wqh : g_wph;

    const int row = tid >> 1;
    const int cp  = (tid & 1) * 2;
    const __half* aHg = AH + (size_t)(mb + row) * K + cp * 8;
    const __half* bHg = BH + (size_t)(nb + row) * K + cp * 8;
    const uint32_t stDst = row * 80 + cp * 16;

    auto load_st = [&](int st, int k0) {
        const uint32_t d = smB + st * HG_STAGE + stDst;
        cp16(d,         aHg + k0); cp16(d + 16,         aHg + k0 + 8);
        cp16(d + 10240, bHg + k0); cp16(d + 10240 + 16, bHg + k0 + 8);
        asm volatile("cp.async.commit_group;\n");
    };

    float acc[2][8][4];
#pragma unroll
    for (int i = 0; i < 2; i++)
#pragma unroll
        for (int j = 0; j < 8; j++)
#pragma unroll
            for (int r = 0; r < 4; r++) acc[i][j][r] = 0.f;

    const uint32_t aOff = (wm + (lane & 15)) * 80 + (lane >> 4) * 16;
    const uint32_t bOff = (wn + (lane & 15)) * 80 + (lane >> 4) * 16 + 10240;

    const int nK = K / 32;
    load_st(0, 0);

    for (int kt = 0; kt < nK; kt++) {
        asm volatile("cp.async.wait_group 0;\n");
        __syncthreads();
        if (kt + 1 < nK) load_st((kt + 1) & 1, (kt + 1) * 32);
        const uint32_t sb = smB + (kt & 1) * HG_STAGE;

#pragma unroll
        for (int s = 0; s < 2; s++) {
            uint32_t ah[2][4];
#pragma unroll
            for (int i = 0; i < 2; i++)
                ldsm4(ah[i][0], ah[i][1], ah[i][2], ah[i][3],
                      sb + aOff + i * 1280 + s * 32);
#pragma unroll
            for (int j = 0; j < 4; j++) {
                uint32_t bh_[4];
                ldsm4(bh_[0], bh_[1], bh_[2], bh_[3],
                      sb + bOff + j * 1280 + s * 32);
#pragma unroll
                for (int i = 0; i < 2; i++) {
                    mma_f16(acc[i][2*j  ], ah[i][0], ah[i][1], ah[i][2], ah[i][3], bh_[0], bh_[2]);
                    mma_f16(acc[i][2*j+1], ah[i][0], ah[i][1], ah[i][2], ah[i][3], bh_[1], bh_[3]);
                }
            }
        }
    }

#pragma unroll
    for (int i = 0; i < 2; i++) {
#pragma unroll
        for (int j = 0; j < 8; j++) {
            const int r0 = mb + wm + i * 16 + gr;
            const int c0 = nb + wn + j * 8 + 2 * tg;     // even
            const float bia0 = bias[c0], bia1 = bias[c0 + 1];
            if (MODE == 1) {
                const int tsel = c0 >> 10, rem = c0 & 1023;
                const int hh = rem >> 6, d = rem & 63;
#pragma unroll
                for (int pr = 0; pr < 2; pr++) {
                    const int m = r0 + pr * 8;
                    const int bb = m >> 10, s = m & 1023;
                    const int bh2 = bb * NHEADS + hh;
                    const float v0 = acc[i][j][pr*2 + 0] + bia0;
                    const float v1 = acc[i][j][pr*2 + 1] + bia1;
                    const uint32_t pk = h2u(__floats2half2_rn(v0, v1));
                    if (tsel < 2) {
                        g_qkT[tsel][bh2][d >> 1][s] = pk;
                    } else {
                        *(float2*)&g_v[bh2][s][d] = make_float2(v0, v1);
                        *(uint32_t*)&g_vh[bh2][s][d] = pk;
                    }
                }
            } else {
                float2 lo = make_float2(acc[i][j][0] + bia0, acc[i][j][1] + bia1);
                float2 hi = make_float2(acc[i][j][2] + bia0, acc[i][j][3] + bia1);
                *(float2*)&C[(size_t)r0 * N + c0]       = lo;
                *(float2*)&C[(size_t)(r0 + 8) * N + c0] = hi;
            }
        }
    }
}

// ==============================================================================
// FUSED Laplacian + attn@v + rownorm + depthwise conv.
// Grid (16 i-tiles of 64 rows, 32 bh), 256 threads / 8 warps, occ 4.
// Per jt (64-j chunk):
//   cp.async stage K(transposed half2) + Vh chunks (1 group/jt, dbl-buffered)
//   dist phase: half2 HSUB2/HADD2-|.| -> exp -> fp16 kern tile in smem + rowsum
//   mma phase: kern_tile(A, ldsm4) @ vh(B, ldsm4t) -> fp32 acc (16 mma/warp/jt)
// Epilogue: acc / rowsum + dwc local branch -> g_yh (fp16).
// smem: qs 8704 | ks 2x8704 | kt 9216 | vh 2x9216 | rsum 256 = 54016 B
// ==============================================================================
#define QS_OFF   0
#define KS_OFF   8704
#define KT_OFF   26112
#define VH_OFF   35328
#define RS_OFF   53760
#define LAP_SMEM 54016

__global__ __launch_bounds__(256, 4) void lap_av(const float* __restrict__ dwc_w,
                                                 const float* __restrict__ dwc_b)
{
    extern __shared__ char sm[];
    const uint32_t smB = smem_u32(sm);

    const int tid  = threadIdx.x;
    const int tx   = tid & 15;
    const int ty   = tid >> 4;
    const int warp = tid >> 5;
    const int lane = tid & 31;
    const int gr   = lane >> 2;
    const int tg   = lane & 3;
    const int wm4  = (warp & 3) * 16;     // warp M offset (4 warps x 16 rows)
    const int wn2  = (warp >> 2) * 32;    // warp N offset (2 warps x 32 cols)
    const int it   = blockIdx.x;          // 0..15
    const int bh   = blockIdx.y;          // 0..31
    const int bb   = bh >> 4;
    const int h    = bh & 15;

    const char* Qt = (const char*)&g_qkT[0][bh][0][0];
    const char* Kt = (const char*)&g_qkT[1][bh][0][0];
    const __half* Vh = &g_vh[bh][0][0];
    const float*  V  = &g_v[bh][0][0];

    // ---- staging (all cp.async; 2 chunks of 16B per array per thread) ----
    auto stage_q = [&]() {
#pragma unroll
        for (int r = 0; r < 2; r++) {
            int idx = tid + r * 256;          // 0..511
            int d2 = idx >> 4, c = idx & 15;
            cp16(smB + QS_OFF + d2 * 272 + c * 16,
                 Qt + ((size_t)d2 * 1024 + it * 64 + c * 4) * 4);
        }
    };
    auto stage_k = [&](int buf, int jt) {
#pragma unroll
        for (int r = 0; r < 2; r++) {
            int idx = tid + r * 256;
            int d2 = idx >> 4, c = idx & 15;
            cp16(smB + KS_OFF + buf * 8704 + d2 * 272 + c * 16,
                 Kt + ((size_t)d2 * 1024 + jt * 64 + c * 4) * 4);
        }
    };
    auto stage_v = [&](int buf, int jt) {
#pragma unroll
        for (int r = 0; r < 2; r++) {
            int idx = tid + r * 256;
            int j = idx >> 3, c = idx & 7;
            cp16(smB + VH_OFF + buf * 9216 + j * 144 + c * 16,
                 (const char*)Vh + ((size_t)(jt * 64 + j) * 64 + c * 8) * 2);
        }
    };

    // mma fragment addresses
    const uint32_t aKt = smB + KT_OFF
        + (wm4 + (lane & 7) + ((lane >> 3) & 1) * 8) * 144 + (lane >> 4) * 16;
    const uint32_t bVh = smB + VH_OFF
        + (lane & 15) * 144 + (lane >> 4) * 16 + wn2 * 2;

    // prologue
    stage_q(); stage_k(0, 0); stage_v(0, 0);
    asm volatile("cp.async.commit_group;\n");

    float rs[4] = {0.f, 0.f, 0.f, 0.f};
    float macc[4][4];
#pragma unroll
    for (int n = 0; n < 4; n++)
#pragma unroll
        for (int e = 0; e < 4; e++) macc[n][e] = 0.f;

    const uint32_t* qsP = (const uint32_t*)(sm + QS_OFF);

    for (int jt = 0; jt < 16; jt++) {
        const int buf = jt & 1;
        asm volatile("cp.async.wait_group 0;\n");
        __syncthreads();                       // staging visible; prev mma done
        if (jt < 15) {
            stage_k(buf ^ 1, jt + 1);
            stage_v(buf ^ 1, jt + 1);
            asm volatile("cp.async.commit_group;\n");
        }

        // ---- dist phase ----
        const uint32_t* ksP = (const uint32_t*)(sm + KS_OFF + buf * 8704);
        __half2 acc[4][4];
#pragma unroll
        for (int ii = 0; ii < 4; ii++)
#pragma unroll
            for (int jj = 0; jj < 4; jj++)
                acc[ii][jj] = __half2half2(__ushort_as_half(0));

#pragma unroll
        for (int d2 = 0; d2 < 32; d2++) {
            uint4 qv = *(const uint4*)(qsP + d2 * 68 + ty * 4);
            uint4 kv = *(const uint4*)(ksP + d2 * 68 + tx * 4);
            uint32_t q2[4] = {qv.x, qv.y, qv.z, qv.w};
            uint32_t k2[4] = {kv.x, kv.y, kv.z, kv.w};
#pragma unroll
            for (int ii = 0; ii < 4; ii++)
#pragma unroll
                for (int jj = 0; jj < 4; jj++)
                    acc[ii][jj] = __hadd2(acc[ii][jj],
                                   __habs2(__hsub2(u2h(q2[ii]), u2h(k2[jj]))));
        }

#pragma unroll
        for (int ii = 0; ii < 4; ii++) {
            float op[4];
#pragma unroll
            for (int jj = 0; jj < 4; jj++) {
                float2 fa = __half22float2(acc[ii][jj]);
                float dist = fa.x + fa.y;
                float kv = __expf(-0.0625f * dist);
                op[jj] = kv;
                rs[ii] += kv;
            }
            *(uint2*)(sm + KT_OFF + (ty*4 + ii) * 144 + tx * 8)
                = make_uint2(h2u(__floats2half2_rn(op[0], op[1])),
                             h2u(__floats2half2_rn(op[2], op[3])));
        }
        __syncthreads();                       // kern tile ready

        // ---- mma phase: macc += kt @ vh[buf] ----
        const uint32_t bB = bVh + buf * 9216;
#pragma unroll
        for (int k16 = 0; k16 < 4; k16++) {
            uint32_t a0, a1, a2, a3;
            ldsm4(a0, a1, a2, a3, aKt + k16 * 32);
#pragma unroll
            for (int nf2 = 0; nf2 < 2; nf2++) {
                uint32_t b0, b1, b2, b3;
                ldsm4t(b0, b1, b2, b3, bB + k16 * 2304 + nf2 * 32);
                mma_f16(macc[2*nf2    ], a0, a1, a2, a3, b0, b1);
                mma_f16(macc[2*nf2 + 1], a0, a1, a2, a3, b2, b3);
            }
        }
    }

    // ---- rowsum reduce -> smem ----
    float* rsum = (float*)(sm + RS_OFF);
#pragma unroll
    for (int ii = 0; ii < 4; ii++) {
        float v = rs[ii];
        v += __shfl_xor_sync(0xffffffffu, v, 1);
        v += __shfl_xor_sync(0xffffffffu, v, 2);
        v += __shfl_xor_sync(0xffffffffu, v, 4);
        v += __shfl_xor_sync(0xffffffffu, v, 8);
        if (tx == 0) rsum[ty*4 + ii] = v;
    }
    __syncthreads();

    // ---- epilogue: normalize + depthwise conv -> g_yh ----
#pragma unroll
    for (int nf = 0; nf < 4; nf++) {
        const int dl = wn2 + nf * 8 + tg * 2;
        const int c  = h * 64 + dl;
        const float w0a = dwc_w[c*3+0], w1a = dwc_w[c*3+1], w2a = dwc_w[c*3+2];
        const float b0a = dwc_b[c];
        const float w0b = dwc_w[c*3+3], w1b = dwc_w[c*3+4], w2b = dwc_w[c*3+5];
        const float b1b = dwc_b[c+1];
#pragma unroll
        for (int half = 0; half < 2; half++) {
            const int il = wm4 + gr + half * 8;
            const int s  = it * 64 + il;
            const float sc = 1.0f / (rsum[il] + 1e-6f);
            float o0 = macc[nf][half*2 + 0] * sc;
            float o1 = macc[nf][half*2 + 1] * sc;
            float2 v0 = *(const float2*)&V[(size_t)s*64 + dl];
            float2 vm = (s > 0)       ? *(const float2*)&V[(size_t)(s-1)*64 + dl]
                                      : make_float2(0.f, 0.f);
            float2 vp = (s < SEQ - 1) ? *(const float2*)&V[(size_t)(s+1)*64 + dl]
                                      : make_float2(0.f, 0.f);
            o0 += w0a*vm.x + w1a*v0.x + w2a*vp.x + b0a;
            o1 += w0b*vm.y + w1b*v0.y + w2b*vp.y + b1b;
            const size_t oidx = (size_t)(bb*SEQ + s) * 1024 + c;
            *(uint32_t*)&g_yh[oidx] = h2u(__floats2half2_rn(o0, o1));
        }
    }
}

// ==============================================================================
extern "C" void kernel_launch(void* const* d_in, const int* in_sizes, int n_in,
                              void* d_out, int out_size)
{
    const float* x      = (const float*)d_in[0];
    const float* qkv_w  = (const float*)d_in[1];
    const float* qkv_b  = (const float*)d_in[2];
    const float* proj_w = (const float*)d_in[3];
    const float* proj_b = (const float*)d_in[4];
    const float* dwc_w  = (const float*)d_in[5];
    const float* dwc_b  = (const float*)d_in[6];
    float* out = (float*)d_out;

    cudaFuncSetAttribute(hgemm_nt<1>, cudaFuncAttributeMaxDynamicSharedMemorySize, HG_SMEM);
    cudaFuncSetAttribute(hgemm_nt<0>, cudaFuncAttributeMaxDynamicSharedMemorySize, HG_SMEM);
    cudaFuncSetAttribute(lap_av,      cudaFuncAttributeMaxDynamicSharedMemorySize, LAP_SMEM);

    // 0) convert x / weights to fp16 scratch
    prep_f16<<<dim3(3072, 3), 256>>>(x, qkv_w, proj_w);
    // 1) qkv projection (fp16 HMMA); q,k -> transposed half2, v -> fp32 + fp16
    hgemm_nt<1><<<dim3(24, 16), 256, HG_SMEM>>>(qkv_b, nullptr, 3072, 1024);
    // 2) FUSED Laplacian kernel + attn@v + rownorm + dwc -> y (fp16)
    lap_av<<<dim3(16, 32), 256, LAP_SMEM>>>(dwc_w, dwc_b);
    // 3) output projection (fp16 HMMA) -> d_out
    hgemm_nt<0><<<dim3(8, 16), 256, HG_SMEM>>>(proj_b, out, 1024, 1024);
}